// round 1
// baseline (speedup 1.0000x reference)
#include <cuda_runtime.h>
#include <cuda_bf16.h>
#include <math.h>

// ---------------------------------------------------------------------------
// Problem constants
// ---------------------------------------------------------------------------
#define NTOK 4096          // B*S
#define HDIM 1024          // hidden
#define IDIM 4096          // intermediate
#define DDIM 64            // adapter bottleneck
#define TTASK 8            // tasks
#define TD 512             // T*D
#define TDB 520            // T*D + T (up_b folded)

// ---------------------------------------------------------------------------
// Scratch (static device globals; no allocation allowed)
// ---------------------------------------------------------------------------
__device__ float g_h   [NTOK * HDIM];   // dense output h
__device__ float g_pre [NTOK * HDIM];   // input + h
__device__ float g_ain [NTOK * HDIM];   // LN(prenorm)
__device__ float g_dr  [NTOK * TD];     // relu(down)  [n, t*D+d]
__device__ float g_q   [NTOK * HDIM];   // query
__device__ float g_qk  [NTOK * HDIM];   // query @ key_w
__device__ float g_e   [NTOK * TD];     // qk @ up_w[t]   [n, t*D+d]
__device__ float g_pdr [NTOK * TDB];    // probs*dr, last T cols = probs
__device__ float g_uw2 [TDB * HDIM];    // up_w transposed [(t,d), h]; rows 512..519 = up_b
__device__ float g_mix [NTOK * HDIM];   // sum_t p * adapter_out
__device__ float g_fus [NTOK * HDIM];   // (mix+h) @ value_w^T

// ---------------------------------------------------------------------------
// GEMM: C[M,N] = A[M,K] @ op(B) (+bias)(relu)(A += A2)
//   BT=true : B is [N,K] row-major (use B^T)   -> C = A B^T
//   BT=false: B is [K,N] row-major             -> C = A B
// 128x128 tile, BK=8, 256 threads, 8x8 per thread.
// Requires M%128==0, N%128==0, K%8==0 (all satisfied here).
// ---------------------------------------------------------------------------
#define BM 128
#define BN 128
#define BKK 8

template<bool BT, bool HASBIAS, bool RELU, bool ADD2>
__global__ void __launch_bounds__(256) gemm128(
    const float* __restrict__ A, const float* __restrict__ A2,
    const float* __restrict__ B, const float* __restrict__ bias,
    float* __restrict__ C, int M, int N, int K)
{
    __shared__ __align__(16) float As[BKK][BM];
    __shared__ __align__(16) float Bs[BKK][BN];

    const int tid = threadIdx.x;
    const int m0  = blockIdx.y * BM;
    const int n0  = blockIdx.x * BN;

    const int ar = tid >> 1;          // 0..127  (row within tile for A/B-T loads)
    const int ac = (tid & 1) << 2;    // 0 or 4  (k offset, float4)
    const int tx = tid & 15;
    const int ty = tid >> 4;

    float acc[8][8];
    #pragma unroll
    for (int i = 0; i < 8; i++)
        #pragma unroll
        for (int j = 0; j < 8; j++) acc[i][j] = 0.0f;

    const float* Ap  = A  + (size_t)(m0 + ar) * K + ac;
    const float* A2p = ADD2 ? (A2 + (size_t)(m0 + ar) * K + ac) : nullptr;

    for (int k0 = 0; k0 < K; k0 += BKK) {
        // --- load A tile (transposed into As[k][m]) ---
        float4 av = *(const float4*)(Ap + k0);
        if (ADD2) {
            float4 a2 = *(const float4*)(A2p + k0);
            av.x += a2.x; av.y += a2.y; av.z += a2.z; av.w += a2.w;
        }
        As[ac + 0][ar] = av.x;
        As[ac + 1][ar] = av.y;
        As[ac + 2][ar] = av.z;
        As[ac + 3][ar] = av.w;

        // --- load B tile into Bs[k][n] ---
        if (BT) {
            float4 bv = *(const float4*)(B + (size_t)(n0 + ar) * K + k0 + ac);
            Bs[ac + 0][ar] = bv.x;
            Bs[ac + 1][ar] = bv.y;
            Bs[ac + 2][ar] = bv.z;
            Bs[ac + 3][ar] = bv.w;
        } else {
            int bk = tid >> 5;             // 0..7
            int bn = (tid & 31) << 2;      // 0..124
            float4 bv = *(const float4*)(B + (size_t)(k0 + bk) * N + n0 + bn);
            *(float4*)&Bs[bk][bn] = bv;
        }
        __syncthreads();

        #pragma unroll
        for (int k = 0; k < BKK; k++) {
            float4 a0 = *(const float4*)&As[k][ty * 4];
            float4 a1 = *(const float4*)&As[k][64 + ty * 4];
            float4 b0 = *(const float4*)&Bs[k][tx * 4];
            float4 b1 = *(const float4*)&Bs[k][64 + tx * 4];
            float a[8] = {a0.x, a0.y, a0.z, a0.w, a1.x, a1.y, a1.z, a1.w};
            float b[8] = {b0.x, b0.y, b0.z, b0.w, b1.x, b1.y, b1.z, b1.w};
            #pragma unroll
            for (int i = 0; i < 8; i++)
                #pragma unroll
                for (int j = 0; j < 8; j++)
                    acc[i][j] = fmaf(a[i], b[j], acc[i][j]);
        }
        __syncthreads();
    }

    // --- epilogue ---
    float4 bl = make_float4(0.f, 0.f, 0.f, 0.f);
    float4 bh = make_float4(0.f, 0.f, 0.f, 0.f);
    if (HASBIAS) {
        bl = *(const float4*)(bias + n0 + tx * 4);
        bh = *(const float4*)(bias + n0 + 64 + tx * 4);
    }
    #pragma unroll
    for (int i = 0; i < 8; i++) {
        int m = m0 + ((i < 4) ? (ty * 4 + i) : (64 + ty * 4 + (i - 4)));
        float4 lo = make_float4(acc[i][0] + bl.x, acc[i][1] + bl.y,
                                acc[i][2] + bl.z, acc[i][3] + bl.w);
        float4 hi = make_float4(acc[i][4] + bh.x, acc[i][5] + bh.y,
                                acc[i][6] + bh.z, acc[i][7] + bh.w);
        if (RELU) {
            lo.x = fmaxf(lo.x, 0.f); lo.y = fmaxf(lo.y, 0.f);
            lo.z = fmaxf(lo.z, 0.f); lo.w = fmaxf(lo.w, 0.f);
            hi.x = fmaxf(hi.x, 0.f); hi.y = fmaxf(hi.y, 0.f);
            hi.z = fmaxf(hi.z, 0.f); hi.w = fmaxf(hi.w, 0.f);
        }
        *(float4*)&C[(size_t)m * N + n0 + tx * 4]       = lo;
        *(float4*)&C[(size_t)m * N + n0 + 64 + tx * 4]  = hi;
    }
}

// ---------------------------------------------------------------------------
// Block reduction (256 threads)
// ---------------------------------------------------------------------------
__device__ __forceinline__ float block_sum256(float v)
{
    __shared__ float buf[8];
    int lane = threadIdx.x & 31, wid = threadIdx.x >> 5;
    #pragma unroll
    for (int o = 16; o > 0; o >>= 1) v += __shfl_xor_sync(0xffffffffu, v, o);
    if (lane == 0) buf[wid] = v;
    __syncthreads();
    float r = buf[0] + buf[1] + buf[2] + buf[3] + buf[4] + buf[5] + buf[6] + buf[7];
    __syncthreads();
    return r;
}

// ---------------------------------------------------------------------------
// add + LayerNorm:  x = x1 + x2;  (optionally write x);  out = LN(x)*g + b
// One block (256 thr) per row of H=1024, float4 per thread.
// ---------------------------------------------------------------------------
template<bool WRITE_PRE>
__global__ void __launch_bounds__(256) add_ln_kernel(
    const float* __restrict__ x1, const float* __restrict__ x2,
    const float* __restrict__ gamma, const float* __restrict__ beta,
    float* __restrict__ pre, float* __restrict__ out)
{
    const int n = blockIdx.x;
    const int tid = threadIdx.x;
    const size_t base = (size_t)n * HDIM;

    float4 a = ((const float4*)(x1 + base))[tid];
    float4 c = ((const float4*)(x2 + base))[tid];
    float4 x = make_float4(a.x + c.x, a.y + c.y, a.z + c.z, a.w + c.w);
    if (WRITE_PRE) ((float4*)(pre + base))[tid] = x;

    float s = x.x + x.y + x.z + x.w;
    s = block_sum256(s);
    const float mu = s * (1.0f / HDIM);

    float d0 = x.x - mu, d1 = x.y - mu, d2 = x.z - mu, d3 = x.w - mu;
    float sq = d0 * d0 + d1 * d1 + d2 * d2 + d3 * d3;
    sq = block_sum256(sq);
    const float rstd = rsqrtf(sq * (1.0f / HDIM) + 1e-12f);

    float4 g4 = ((const float4*)gamma)[tid];
    float4 b4 = ((const float4*)beta)[tid];
    float4 o = make_float4(d0 * rstd * g4.x + b4.x,
                           d1 * rstd * g4.y + b4.y,
                           d2 * rstd * g4.z + b4.z,
                           d3 * rstd * g4.w + b4.w);
    ((float4*)(out + base))[tid] = o;
}

// ---------------------------------------------------------------------------
// Build uw2[(t*D+d), h] = up_w[t, h, d];   uw2[512+t, h] = up_b[t, h]
// ---------------------------------------------------------------------------
__global__ void build_uw2_kernel(const float* __restrict__ up_w,
                                 const float* __restrict__ up_b,
                                 float* __restrict__ uw2)
{
    int idx = blockIdx.x * blockDim.x + threadIdx.x;
    if (idx >= TDB * HDIM) return;
    int j = idx >> 10;          // 0..519
    int h = idx & (HDIM - 1);
    float v;
    if (j < TD) {
        int t = j >> 6, d = j & 63;
        v = up_w[((size_t)t * HDIM + h) * DDIM + d];
    } else {
        v = up_b[(size_t)(j - TD) * HDIM + h];
    }
    uw2[idx] = v;
}

// ---------------------------------------------------------------------------
// Scores + softmax over tasks + build pdr.
// One block (256 thr = 8 warps) per token n. Warp w owns task t=w:
//   s[t] = sum_d dr[n,t,d]*e[n,t,d]  +  sum_h qk[n,h]*up_b[t,h]
// (query·key_b term is constant over t -> cancels in softmax, dropped)
// Then probs = softmax_t(s); pdr[n, t*D+d] = probs[t]*dr[n,t,d];
// pdr[n, 512+t] = probs[t].
// ---------------------------------------------------------------------------
__global__ void __launch_bounds__(256) score_softmax_kernel(
    const float* __restrict__ dr, const float* __restrict__ e,
    const float* __restrict__ qk, const float* __restrict__ up_b,
    float* __restrict__ pdr)
{
    const int n = blockIdx.x;
    const int tid = threadIdx.x;
    const int w = tid >> 5, l = tid & 31;

    const size_t b512 = (size_t)n * TD;
    float v = dr[b512 + w * 64 + l]      * e[b512 + w * 64 + l]
            + dr[b512 + w * 64 + 32 + l] * e[b512 + w * 64 + 32 + l];

    // up_b contribution (zeros in practice, kept for generality)
    const float* qrow = qk + (size_t)n * HDIM;
    const float* ub   = up_b + (size_t)w * HDIM;
    float u = 0.f;
    #pragma unroll 8
    for (int h = l; h < HDIM; h += 32) u += qrow[h] * ub[h];
    v += u;

    #pragma unroll
    for (int o = 16; o > 0; o >>= 1) v += __shfl_xor_sync(0xffffffffu, v, o);

    __shared__ float s[TTASK];
    if (l == 0) s[w] = v;
    __syncthreads();

    // every thread computes the 8-way softmax redundantly
    float mx = s[0];
    #pragma unroll
    for (int t = 1; t < TTASK; t++) mx = fmaxf(mx, s[t]);
    float p[TTASK]; float sum = 0.f;
    #pragma unroll
    for (int t = 0; t < TTASK; t++) { p[t] = __expf(s[t] - mx); sum += p[t]; }
    const float inv = 1.0f / sum;

    const size_t b520 = (size_t)n * TDB;
    #pragma unroll
    for (int r = 0; r < 2; r++) {
        int c = tid + r * 256;              // 0..511
        int t = c >> 6;
        pdr[b520 + c] = p[t] * inv * dr[b512 + c];
    }
    if (tid < TTASK) pdr[b520 + TD + tid] = p[tid] * inv;
}

// ---------------------------------------------------------------------------
// Launch
// ---------------------------------------------------------------------------
struct Scratch {
    float *h, *pre, *ain, *dr, *q, *qk, *e, *pdr, *uw2, *mix, *fus;
};

static Scratch get_scratch()
{
    Scratch s;
    cudaGetSymbolAddress((void**)&s.h,   g_h);
    cudaGetSymbolAddress((void**)&s.pre, g_pre);
    cudaGetSymbolAddress((void**)&s.ain, g_ain);
    cudaGetSymbolAddress((void**)&s.dr,  g_dr);
    cudaGetSymbolAddress((void**)&s.q,   g_q);
    cudaGetSymbolAddress((void**)&s.qk,  g_qk);
    cudaGetSymbolAddress((void**)&s.e,   g_e);
    cudaGetSymbolAddress((void**)&s.pdr, g_pdr);
    cudaGetSymbolAddress((void**)&s.uw2, g_uw2);
    cudaGetSymbolAddress((void**)&s.mix, g_mix);
    cudaGetSymbolAddress((void**)&s.fus, g_fus);
    return s;
}

extern "C" void kernel_launch(void* const* d_in, const int* in_sizes, int n_in,
                              void* d_out, int out_size)
{
    const float* hs      = (const float*)d_in[0];   // [N, I]
    const float* inp     = (const float*)d_in[1];   // [N, H]
    const float* dense_w = (const float*)d_in[2];   // [H, I]
    const float* dense_b = (const float*)d_in[3];   // [H]
    const float* ln_g    = (const float*)d_in[4];   // [H]
    const float* ln_b    = (const float*)d_in[5];   // [H]
    const float* down_w  = (const float*)d_in[6];   // [T, D, H] -> flat [512, H]
    const float* down_b  = (const float*)d_in[7];   // [T, D]    -> flat [512]
    const float* up_w    = (const float*)d_in[8];   // [T, H, D]
    const float* up_b    = (const float*)d_in[9];   // [T, H]
    const float* key_w   = (const float*)d_in[10];  // [H, H]
    /* key_b d_in[11] cancels in softmax */
    const float* query_w = (const float*)d_in[12];  // [H, H]
    const float* query_b = (const float*)d_in[13];  // [H]
    const float* value_w = (const float*)d_in[14];  // [H, H]
    float* out = (float*)d_out;

    // Resolved once (outside graph capture: first call is the correctness run)
    static Scratch s = get_scratch();

    dim3 blk(256);

    // 0. transpose up_w (+up_b rows) -> uw2
    build_uw2_kernel<<<(TDB * HDIM + 255) / 256, blk>>>(up_w, up_b, s.uw2);

    // 1. h = hs @ dense_w^T + dense_b          [N,H], K=I
    gemm128<true, true, false, false><<<dim3(HDIM / BN, NTOK / BM), blk>>>(
        hs, nullptr, dense_w, dense_b, s.h, NTOK, HDIM, IDIM);

    // 2. pre = inp + h; ain = LN(pre)
    add_ln_kernel<true><<<NTOK, blk>>>(inp, s.h, ln_g, ln_b, s.pre, s.ain);

    // 3. dr = relu(ain @ down_w_flat^T + down_b_flat)   [N,512], K=H
    gemm128<true, true, true, false><<<dim3(TD / BN, NTOK / BM), blk>>>(
        s.ain, nullptr, down_w, down_b, s.dr, NTOK, TD, HDIM);

    // 4. q = pre @ query_w^T + query_b         [N,H], K=H
    gemm128<true, true, false, false><<<dim3(HDIM / BN, NTOK / BM), blk>>>(
        s.pre, nullptr, query_w, query_b, s.q, NTOK, HDIM, HDIM);

    // 5. qk = q @ key_w                        [N,H], K=H (B not transposed)
    gemm128<false, false, false, false><<<dim3(HDIM / BN, NTOK / BM), blk>>>(
        s.q, nullptr, key_w, nullptr, s.qk, NTOK, HDIM, HDIM);

    // 6. e = qk @ uw2[0:512]^T                 [N,512], K=H
    gemm128<true, false, false, false><<<dim3(TD / BN, NTOK / BM), blk>>>(
        s.qk, nullptr, s.uw2, nullptr, s.e, NTOK, TD, HDIM);

    // 7. scores + softmax + pdr
    score_softmax_kernel<<<NTOK, blk>>>(s.dr, s.e, s.qk, up_b, s.pdr);

    // 8. mix = pdr @ uw2                       [N,H], K=520
    gemm128<false, false, false, false><<<dim3(HDIM / BN, NTOK / BM), blk>>>(
        s.pdr, nullptr, s.uw2, nullptr, s.mix, NTOK, HDIM, TDB);

    // 9. fus = (mix + h) @ value_w^T           [N,H], K=H
    gemm128<true, false, false, true><<<dim3(HDIM / BN, NTOK / BM), blk>>>(
        s.mix, s.h, value_w, nullptr, s.fus, NTOK, HDIM, HDIM);

    // 10. out = LN(inp + fus)
    add_ln_kernel<false><<<NTOK, blk>>>(inp, s.fus, ln_g, ln_b, nullptr, out);
}

// round 4
// speedup vs baseline: 3.0724x; 3.0724x over previous
#include <cuda_runtime.h>
#include <cuda_bf16.h>
#include <math.h>
#include <stdint.h>

// ---------------------------------------------------------------------------
// Problem constants
// ---------------------------------------------------------------------------
#define NTOK 4096          // B*S
#define HDIM 1024          // hidden
#define IDIM 4096          // intermediate
#define DDIM 64            // adapter bottleneck
#define TTASK 8            // tasks
#define TD 512             // T*D
#define TDBP 544           // T*D + T (up_b folded) padded to multiple of 32

// ---------------------------------------------------------------------------
// Scratch (static device globals; no allocation allowed)
// ---------------------------------------------------------------------------
__device__ float g_h   [NTOK * HDIM];   // dense output h
__device__ float g_pre [NTOK * HDIM];   // input + h
__device__ float g_ain [NTOK * HDIM];   // LN(prenorm)
__device__ float g_dr  [NTOK * TD];     // relu(down)  [n, t*D+d]
__device__ float g_q   [NTOK * HDIM];   // query
__device__ float g_qk  [NTOK * HDIM];   // query @ key_w
__device__ float g_e   [NTOK * TD];     // qk @ up_w[t]   [n, t*D+d]
__device__ float g_pdr [NTOK * TDBP];   // probs*dr, cols 512..519 = probs, 520..543 = 0
__device__ float g_uw2 [TDBP * HDIM];   // up_w transposed [(t,d), h]; rows 512..519 = up_b; 520.. = 0
__device__ float g_mix [NTOK * HDIM];   // sum_t p * adapter_out  (+h in epilogue)
__device__ float g_fus [NTOK * HDIM];   // mix @ value_w^T

// ---------------------------------------------------------------------------
// Async-copy / MMA helpers
// ---------------------------------------------------------------------------
__device__ __forceinline__ void cp_async16(void* smem, const void* gmem) {
    uint32_t s = (uint32_t)__cvta_generic_to_shared(smem);
    asm volatile("cp.async.cg.shared.global [%0], [%1], 16;\n" :: "r"(s), "l"(gmem));
}
__device__ __forceinline__ void cp_commit() {
    asm volatile("cp.async.commit_group;\n");
}
template<int W> __device__ __forceinline__ void cp_wait() {
    asm volatile("cp.async.wait_group %0;\n" :: "n"(W));
}
__device__ __forceinline__ uint32_t f2tf(float f) {
    uint32_t u;
    asm("cvt.rna.tf32.f32 %0, %1;\n" : "=r"(u) : "f"(f));
    return u;
}
__device__ __forceinline__ void mma_tf32(float* c, const uint32_t* a, const uint32_t* b) {
    asm volatile(
        "mma.sync.aligned.m16n8k8.row.col.f32.tf32.tf32.f32 "
        "{%0,%1,%2,%3}, {%4,%5,%6,%7}, {%8,%9}, {%0,%1,%2,%3};\n"
        : "+f"(c[0]), "+f"(c[1]), "+f"(c[2]), "+f"(c[3])
        : "r"(a[0]), "r"(a[1]), "r"(a[2]), "r"(a[3]), "r"(b[0]), "r"(b[1]));
}

// ---------------------------------------------------------------------------
// tf32 tensor-core GEMM: C[M,N] = A[M,K] @ op(B) (+bias)(relu)(+C2)
//   BT=true : B is [N,K] row-major -> C = A B^T
//   BT=false: B is [K,N] row-major -> C = A B
// 128x128 CTA tile, BK=32, 256 threads (8 warps, 2x4), warp tile 64x32.
// 3-stage cp.async pipeline. Requires M%128==0, N%128==0, K%32==0, K>=64.
// ---------------------------------------------------------------------------
#define SA_STG (128 * 36)                 // A stage floats (pad 4/row)
#define SB_STG_T (128 * 36)               // B stage (BT=1: [n][k], pad 4)
#define SB_STG_N (32 * 136)               // B stage (BT=0: [k][n], pad 8)

template<bool BT, bool HASBIAS, bool RELU, bool ADDC>
__global__ void __launch_bounds__(256) gemm_tf32(
    const float* __restrict__ A, const float* __restrict__ B,
    const float* __restrict__ bias, const float* __restrict__ C2,
    float* __restrict__ C, int M, int N, int K)
{
    constexpr int SB = BT ? SB_STG_T : SB_STG_N;
    extern __shared__ float sm[];
    float* As = sm;                 // [3][SA_STG]
    float* Bs = sm + 3 * SA_STG;    // [3][SB]

    const int tid  = threadIdx.x;
    const int m0   = blockIdx.y * 128;
    const int n0   = blockIdx.x * 128;
    const int w    = tid >> 5;
    const int lane = tid & 31;
    const int qr   = lane >> 2;     // 0..7
    const int qc   = lane & 3;      // 0..3
    const int wm   = (w & 1) * 64;  // warp m offset in tile
    const int wn   = (w >> 1) * 32; // warp n offset in tile

    const int nt = K >> 5;

    auto copy_stage = [&](int s, int k0) {
        float* da = As + s * SA_STG;
        #pragma unroll
        for (int i = 0; i < 4; i++) {
            int g = tid + 256 * i;
            int r = g >> 3, c = (g & 7) << 2;
            cp_async16(da + r * 36 + c, A + (size_t)(m0 + r) * K + k0 + c);
        }
        float* db = Bs + s * SB;
        if (BT) {
            #pragma unroll
            for (int i = 0; i < 4; i++) {
                int g = tid + 256 * i;
                int r = g >> 3, c = (g & 7) << 2;
                cp_async16(db + r * 36 + c, B + (size_t)(n0 + r) * K + k0 + c);
            }
        } else {
            #pragma unroll
            for (int i = 0; i < 4; i++) {
                int g = tid + 256 * i;
                int r = g >> 5, c = (g & 31) << 2;
                cp_async16(db + r * 136 + c, B + (size_t)(k0 + r) * N + n0 + c);
            }
        }
    };

    float acc[4][4][4];
    #pragma unroll
    for (int mi = 0; mi < 4; mi++)
        #pragma unroll
        for (int nj = 0; nj < 4; nj++)
            #pragma unroll
            for (int r = 0; r < 4; r++) acc[mi][nj][r] = 0.0f;

    copy_stage(0, 0);  cp_commit();
    copy_stage(1, 32); cp_commit();

    for (int t = 0; t < nt; t++) {
        cp_wait<1>();
        __syncthreads();
        // Prefetch stage t+2 into buffer (t+2)%3 (held stage t-1, fully consumed).
        if (t + 2 < nt) copy_stage((t + 2) % 3, (t + 2) * 32);
        cp_commit();

        const float* a = As + (t % 3) * SA_STG;
        const float* b = Bs + (t % 3) * SB;

        #pragma unroll
        for (int ks = 0; ks < 4; ks++) {
            const int kk = ks * 8;
            uint32_t af[4][4], bf[4][2];
            #pragma unroll
            for (int mi = 0; mi < 4; mi++) {
                const int am = wm + mi * 16;
                af[mi][0] = f2tf(a[(am + qr    ) * 36 + kk + qc    ]);
                af[mi][1] = f2tf(a[(am + qr + 8) * 36 + kk + qc    ]);
                af[mi][2] = f2tf(a[(am + qr    ) * 36 + kk + qc + 4]);
                af[mi][3] = f2tf(a[(am + qr + 8) * 36 + kk + qc + 4]);
            }
            #pragma unroll
            for (int nj = 0; nj < 4; nj++) {
                const int bn = wn + nj * 8;
                if (BT) {
                    bf[nj][0] = f2tf(b[(bn + qr) * 36 + kk + qc    ]);
                    bf[nj][1] = f2tf(b[(bn + qr) * 36 + kk + qc + 4]);
                } else {
                    bf[nj][0] = f2tf(b[(kk + qc    ) * 136 + bn + qr]);
                    bf[nj][1] = f2tf(b[(kk + qc + 4) * 136 + bn + qr]);
                }
            }
            #pragma unroll
            for (int mi = 0; mi < 4; mi++)
                #pragma unroll
                for (int nj = 0; nj < 4; nj++)
                    mma_tf32(acc[mi][nj], af[mi], bf[nj]);
        }
    }

    // ----- epilogue -----
    float2 bv[4];
    if (HASBIAS) {
        #pragma unroll
        for (int nj = 0; nj < 4; nj++)
            bv[nj] = *(const float2*)&bias[n0 + wn + nj * 8 + qc * 2];
    }
    #pragma unroll
    for (int mi = 0; mi < 4; mi++) {
        const int r0 = m0 + wm + mi * 16 + qr;
        #pragma unroll
        for (int nj = 0; nj < 4; nj++) {
            const int cc = n0 + wn + nj * 8 + qc * 2;
            float2 v0 = make_float2(acc[mi][nj][0], acc[mi][nj][1]);
            float2 v1 = make_float2(acc[mi][nj][2], acc[mi][nj][3]);
            if (HASBIAS) {
                v0.x += bv[nj].x; v0.y += bv[nj].y;
                v1.x += bv[nj].x; v1.y += bv[nj].y;
            }
            if (ADDC) {
                float2 c0 = *(const float2*)&C2[(size_t)r0 * N + cc];
                float2 c1 = *(const float2*)&C2[(size_t)(r0 + 8) * N + cc];
                v0.x += c0.x; v0.y += c0.y;
                v1.x += c1.x; v1.y += c1.y;
            }
            if (RELU) {
                v0.x = fmaxf(v0.x, 0.f); v0.y = fmaxf(v0.y, 0.f);
                v1.x = fmaxf(v1.x, 0.f); v1.y = fmaxf(v1.y, 0.f);
            }
            *(float2*)&C[(size_t)r0 * N + cc]       = v0;
            *(float2*)&C[(size_t)(r0 + 8) * N + cc] = v1;
        }
    }
}

// ---------------------------------------------------------------------------
// Block reduction (256 threads)
// ---------------------------------------------------------------------------
__device__ __forceinline__ float block_sum256(float v)
{
    __shared__ float buf[8];
    int lane = threadIdx.x & 31, wid = threadIdx.x >> 5;
    #pragma unroll
    for (int o = 16; o > 0; o >>= 1) v += __shfl_xor_sync(0xffffffffu, v, o);
    if (lane == 0) buf[wid] = v;
    __syncthreads();
    float r = buf[0] + buf[1] + buf[2] + buf[3] + buf[4] + buf[5] + buf[6] + buf[7];
    __syncthreads();
    return r;
}

// ---------------------------------------------------------------------------
// add + LayerNorm:  x = x1 + x2;  (optionally write x);  out = LN(x)*g + b
// ---------------------------------------------------------------------------
template<bool WRITE_PRE>
__global__ void __launch_bounds__(256) add_ln_kernel(
    const float* __restrict__ x1, const float* __restrict__ x2,
    const float* __restrict__ gamma, const float* __restrict__ beta,
    float* __restrict__ pre, float* __restrict__ out)
{
    const int n = blockIdx.x;
    const int tid = threadIdx.x;
    const size_t base = (size_t)n * HDIM;

    float4 a = ((const float4*)(x1 + base))[tid];
    float4 c = ((const float4*)(x2 + base))[tid];
    float4 x = make_float4(a.x + c.x, a.y + c.y, a.z + c.z, a.w + c.w);
    if (WRITE_PRE) ((float4*)(pre + base))[tid] = x;

    float s = x.x + x.y + x.z + x.w;
    s = block_sum256(s);
    const float mu = s * (1.0f / HDIM);

    float d0 = x.x - mu, d1 = x.y - mu, d2 = x.z - mu, d3 = x.w - mu;
    float sq = d0 * d0 + d1 * d1 + d2 * d2 + d3 * d3;
    sq = block_sum256(sq);
    const float rstd = rsqrtf(sq * (1.0f / HDIM) + 1e-12f);

    float4 g4 = ((const float4*)gamma)[tid];
    float4 b4 = ((const float4*)beta)[tid];
    float4 o = make_float4(d0 * rstd * g4.x + b4.x,
                           d1 * rstd * g4.y + b4.y,
                           d2 * rstd * g4.z + b4.z,
                           d3 * rstd * g4.w + b4.w);
    ((float4*)(out + base))[tid] = o;
}

// ---------------------------------------------------------------------------
// uw2[(t*D+d), h] = up_w[t, h, d]; uw2[512+t, h] = up_b[t, h]; rows 520..543 = 0
// ---------------------------------------------------------------------------
__global__ void build_uw2_kernel(const float* __restrict__ up_w,
                                 const float* __restrict__ up_b,
                                 float* __restrict__ uw2)
{
    int idx = blockIdx.x * blockDim.x + threadIdx.x;
    if (idx >= TDBP * HDIM) return;
    int j = idx >> 10;          // 0..543
    int h = idx & (HDIM - 1);
    float v = 0.0f;
    if (j < TD) {
        int t = j >> 6, d = j & 63;
        v = up_w[((size_t)t * HDIM + h) * DDIM + d];
    } else if (j < TD + TTASK) {
        v = up_b[(size_t)(j - TD) * HDIM + h];
    }
    uw2[idx] = v;
}

// ---------------------------------------------------------------------------
// Scores + softmax over tasks + build pdr (stride TDBP).
//   s[t] = sum_d dr[n,t,d]*e[n,t,d] + sum_h qk[n,h]*up_b[t,h]
// (query . key_b term is constant over t -> cancels in softmax)
// pdr[n, t*D+d] = probs[t]*dr; pdr[n,512+t] = probs[t]; pdr[n,520..543]=0
// ---------------------------------------------------------------------------
__global__ void __launch_bounds__(256) score_softmax_kernel(
    const float* __restrict__ dr, const float* __restrict__ e,
    const float* __restrict__ qk, const float* __restrict__ up_b,
    float* __restrict__ pdr)
{
    const int n = blockIdx.x;
    const int tid = threadIdx.x;
    const int w = tid >> 5, l = tid & 31;

    const size_t b512 = (size_t)n * TD;
    float v = dr[b512 + w * 64 + l]      * e[b512 + w * 64 + l]
            + dr[b512 + w * 64 + 32 + l] * e[b512 + w * 64 + 32 + l];

    const float* qrow = qk + (size_t)n * HDIM;
    const float* ub   = up_b + (size_t)w * HDIM;
    float u = 0.f;
    #pragma unroll 8
    for (int h = l; h < HDIM; h += 32) u += qrow[h] * ub[h];
    v += u;

    #pragma unroll
    for (int o = 16; o > 0; o >>= 1) v += __shfl_xor_sync(0xffffffffu, v, o);

    __shared__ float s[TTASK];
    if (l == 0) s[w] = v;
    __syncthreads();

    float mx = s[0];
    #pragma unroll
    for (int t = 1; t < TTASK; t++) mx = fmaxf(mx, s[t]);
    float p[TTASK]; float sum = 0.f;
    #pragma unroll
    for (int t = 0; t < TTASK; t++) { p[t] = __expf(s[t] - mx); sum += p[t]; }
    const float inv = 1.0f / sum;

    const size_t b = (size_t)n * TDBP;
    #pragma unroll
    for (int r = 0; r < 2; r++) {
        int c = tid + r * 256;              // 0..511
        int t = c >> 6;
        pdr[b + c] = p[t] * inv * dr[b512 + c];
    }
    if (tid < TTASK)       pdr[b + TD + tid]          = p[tid] * inv;
    else if (tid < 32)     pdr[b + TD + TTASK + (tid - TTASK)] = 0.0f;  // pad cols 520..543
}

// ---------------------------------------------------------------------------
// Launch
// ---------------------------------------------------------------------------
struct Scratch {
    float *h, *pre, *ain, *dr, *q, *qk, *e, *pdr, *uw2, *mix, *fus;
};

static constexpr int SMEM_BT1 = 3 * (SA_STG + SB_STG_T) * 4;  // 110592 B
static constexpr int SMEM_BT0 = 3 * (SA_STG + SB_STG_N) * 4;  // 107520 B

static Scratch init_once()
{
    Scratch s;
    cudaGetSymbolAddress((void**)&s.h,   g_h);
    cudaGetSymbolAddress((void**)&s.pre, g_pre);
    cudaGetSymbolAddress((void**)&s.ain, g_ain);
    cudaGetSymbolAddress((void**)&s.dr,  g_dr);
    cudaGetSymbolAddress((void**)&s.q,   g_q);
    cudaGetSymbolAddress((void**)&s.qk,  g_qk);
    cudaGetSymbolAddress((void**)&s.e,   g_e);
    cudaGetSymbolAddress((void**)&s.pdr, g_pdr);
    cudaGetSymbolAddress((void**)&s.uw2, g_uw2);
    cudaGetSymbolAddress((void**)&s.mix, g_mix);
    cudaGetSymbolAddress((void**)&s.fus, g_fus);
    cudaFuncSetAttribute(gemm_tf32<true,  true,  false, false>, cudaFuncAttributeMaxDynamicSharedMemorySize, SMEM_BT1);
    cudaFuncSetAttribute(gemm_tf32<true,  true,  true,  false>, cudaFuncAttributeMaxDynamicSharedMemorySize, SMEM_BT1);
    cudaFuncSetAttribute(gemm_tf32<true,  false, false, false>, cudaFuncAttributeMaxDynamicSharedMemorySize, SMEM_BT1);
    cudaFuncSetAttribute(gemm_tf32<false, false, false, false>, cudaFuncAttributeMaxDynamicSharedMemorySize, SMEM_BT0);
    cudaFuncSetAttribute(gemm_tf32<false, false, false, true >, cudaFuncAttributeMaxDynamicSharedMemorySize, SMEM_BT0);
    return s;
}

extern "C" void kernel_launch(void* const* d_in, const int* in_sizes, int n_in,
                              void* d_out, int out_size)
{
    const float* hs      = (const float*)d_in[0];   // [N, I]
    const float* inp     = (const float*)d_in[1];   // [N, H]
    const float* dense_w = (const float*)d_in[2];   // [H, I]
    const float* dense_b = (const float*)d_in[3];   // [H]
    const float* ln_g    = (const float*)d_in[4];   // [H]
    const float* ln_b    = (const float*)d_in[5];   // [H]
    const float* down_w  = (const float*)d_in[6];   // [T, D, H] -> flat [512, H]
    const float* down_b  = (const float*)d_in[7];   // [T, D]    -> flat [512]
    const float* up_w    = (const float*)d_in[8];   // [T, H, D]
    const float* up_b    = (const float*)d_in[9];   // [T, H]
    const float* key_w   = (const float*)d_in[10];  // [H, H] (key_b cancels)
    const float* query_w = (const float*)d_in[12];  // [H, H]
    const float* query_b = (const float*)d_in[13];  // [H]
    const float* value_w = (const float*)d_in[14];  // [H, H]
    float* out = (float*)d_out;

    static Scratch s = init_once();

    dim3 blk(256);

    // 0. transpose up_w (+up_b rows, zero pad) -> uw2
    build_uw2_kernel<<<(TDBP * HDIM + 255) / 256, blk>>>(up_w, up_b, s.uw2);

    // 1. h = hs @ dense_w^T + dense_b          [N,H], K=I
    gemm_tf32<true, true, false, false><<<dim3(HDIM / 128, NTOK / 128), blk, SMEM_BT1>>>(
        hs, dense_w, dense_b, nullptr, s.h, NTOK, HDIM, IDIM);

    // 2. pre = inp + h; ain = LN(pre)
    add_ln_kernel<true><<<NTOK, blk>>>(inp, s.h, ln_g, ln_b, s.pre, s.ain);

    // 3. dr = relu(ain @ down_w^T + down_b)    [N,512], K=H
    gemm_tf32<true, true, true, false><<<dim3(TD / 128, NTOK / 128), blk, SMEM_BT1>>>(
        s.ain, down_w, down_b, nullptr, s.dr, NTOK, TD, HDIM);

    // 4. q = pre @ query_w^T + query_b         [N,H], K=H
    gemm_tf32<true, true, false, false><<<dim3(HDIM / 128, NTOK / 128), blk, SMEM_BT1>>>(
        s.pre, query_w, query_b, nullptr, s.q, NTOK, HDIM, HDIM);

    // 5. qk = q @ key_w                        [N,H], K=H
    gemm_tf32<false, false, false, false><<<dim3(HDIM / 128, NTOK / 128), blk, SMEM_BT0>>>(
        s.q, key_w, nullptr, nullptr, s.qk, NTOK, HDIM, HDIM);

    // 6. e = qk @ uw2[0:512]^T                 [N,512], K=H
    gemm_tf32<true, false, false, false><<<dim3(TD / 128, NTOK / 128), blk, SMEM_BT1>>>(
        s.qk, s.uw2, nullptr, nullptr, s.e, NTOK, TD, HDIM);

    // 7. scores + softmax + pdr (incl. zero pad cols)
    score_softmax_kernel<<<NTOK, blk>>>(s.dr, s.e, s.qk, up_b, s.pdr);

    // 8. mix = pdr @ uw2 + h                   [N,H], K=544 (epilogue +h)
    gemm_tf32<false, false, false, true><<<dim3(HDIM / 128, NTOK / 128), blk, SMEM_BT0>>>(
        s.pdr, s.uw2, nullptr, s.h, s.mix, NTOK, HDIM, TDBP);

    // 9. fus = mix @ value_w^T                 [N,H], K=H
    gemm_tf32<true, false, false, false><<<dim3(HDIM / 128, NTOK / 128), blk, SMEM_BT1>>>(
        s.mix, value_w, nullptr, nullptr, s.fus, NTOK, HDIM, HDIM);

    // 10. out = LN(inp + fus)
    add_ln_kernel<false><<<NTOK, blk>>>(inp, s.fus, ln_g, ln_b, nullptr, out);
}

// round 5
// speedup vs baseline: 3.2978x; 1.0734x over previous
#include <cuda_runtime.h>
#include <cuda_bf16.h>
#include <math.h>
#include <stdint.h>

// ---------------------------------------------------------------------------
// Problem constants
// ---------------------------------------------------------------------------
#define NTOK 4096          // B*S
#define HDIM 1024          // hidden
#define IDIM 4096          // intermediate
#define DDIM 64            // adapter bottleneck
#define TTASK 8            // tasks
#define TD 512             // T*D
#define TDBP 544           // T*D + T (up_b folded) padded to multiple of 32

// ---------------------------------------------------------------------------
// Scratch (static device globals; no allocation allowed)
// ---------------------------------------------------------------------------
__device__ float g_h   [NTOK * HDIM];   // dense output h (fp32, residual path)
__device__ float g_pre [NTOK * HDIM];   // input + h (tf32-rounded; only GEMM A)
__device__ float g_ain [NTOK * HDIM];   // LN(prenorm) (tf32-rounded; only GEMM A)
__device__ float g_dr  [NTOK * TD];     // relu(down) fp32
__device__ float g_q   [NTOK * HDIM];   // query (tf32-rounded)
__device__ float g_qk  [NTOK * HDIM];   // query @ key_w (tf32-rounded)
__device__ float g_e   [NTOK * TD];     // qk @ up_w[t] fp32
__device__ float g_pdr [NTOK * TDBP];   // probs*dr (tf32-rounded), cols 512..519 = probs
__device__ float g_uw2 [TDBP * HDIM];   // up_w^T (+up_b rows) tf32-rounded
__device__ float g_mix [NTOK * HDIM];   // pdr@uw2 + h (tf32-rounded; only GEMM A)
__device__ float g_fus [NTOK * HDIM];   // mix @ value_w^T fp32
// tf32-rounded weight copies
__device__ float g_dw  [HDIM * IDIM];   // dense_w
__device__ float g_dnw [TD * HDIM];     // down_w
__device__ float g_qw  [HDIM * HDIM];   // query_w
__device__ float g_kw  [HDIM * HDIM];   // key_w
__device__ float g_vw  [HDIM * HDIM];   // value_w

// ---------------------------------------------------------------------------
// Async-copy / MMA helpers
// ---------------------------------------------------------------------------
__device__ __forceinline__ void cp_async16(void* smem, const void* gmem) {
    uint32_t s = (uint32_t)__cvta_generic_to_shared(smem);
    asm volatile("cp.async.cg.shared.global [%0], [%1], 16;\n" :: "r"(s), "l"(gmem));
}
__device__ __forceinline__ void cp_commit() {
    asm volatile("cp.async.commit_group;\n");
}
template<int W> __device__ __forceinline__ void cp_wait() {
    asm volatile("cp.async.wait_group %0;\n" :: "n"(W));
}
__device__ __forceinline__ uint32_t f2tf(float f) {
    uint32_t u;
    asm("cvt.rna.tf32.f32 %0, %1;\n" : "=r"(u) : "f"(f));
    return u;
}
__device__ __forceinline__ float roundtf(float f) {
    return __uint_as_float(f2tf(f));
}
template<bool CVT>
__device__ __forceinline__ uint32_t ldfrag(const float* p) {
    float v = *p;
    if (CVT) return f2tf(v);
    return __float_as_uint(v);
}
__device__ __forceinline__ void mma_tf32(float* c, const uint32_t* a, const uint32_t* b) {
    asm volatile(
        "mma.sync.aligned.m16n8k8.row.col.f32.tf32.tf32.f32 "
        "{%0,%1,%2,%3}, {%4,%5,%6,%7}, {%8,%9}, {%0,%1,%2,%3};\n"
        : "+f"(c[0]), "+f"(c[1]), "+f"(c[2]), "+f"(c[3])
        : "r"(a[0]), "r"(a[1]), "r"(a[2]), "r"(a[3]), "r"(b[0]), "r"(b[1]));
}

// ---------------------------------------------------------------------------
// tf32 tensor-core GEMM: C[M,N] = A[M,K] @ op(B) (+bias)(relu)(+C2)(round)
//   BT=true : B is [N,K] row-major -> C = A B^T
//   BT=false: B is [K,N] row-major -> C = A B
//   ACVT    : cvt A fragments to tf32 in-loop (else A is pre-rounded)
//   RND     : round output to tf32 (it feeds a later GEMM as A)
// 128x128 CTA tile, BK=32, 256 threads (8 warps, 2x4), warp tile 64x32.
// 2-stage cp.async pipeline, 2 CTAs/SM. M%128==0, N%128==0, K%32==0, K>=64.
// ---------------------------------------------------------------------------
#define SA_STG (128 * 36)                 // A stage floats (pad 4/row)
#define SB_STG_T (128 * 36)               // B stage (BT=1: [n][k], pad 4)
#define SB_STG_N (32 * 136)               // B stage (BT=0: [k][n], pad 8)

template<bool BT, bool ACVT, bool HASBIAS, bool RELU, bool ADDC, bool RND>
__global__ void __launch_bounds__(256, 2) gemm_tf32(
    const float* __restrict__ A, const float* __restrict__ B,
    const float* __restrict__ bias, const float* __restrict__ C2,
    float* __restrict__ C, int M, int N, int K)
{
    constexpr int SB = BT ? SB_STG_T : SB_STG_N;
    extern __shared__ float sm[];
    float* As = sm;                 // [2][SA_STG]
    float* Bs = sm + 2 * SA_STG;    // [2][SB]

    const int tid  = threadIdx.x;
    const int m0   = blockIdx.y * 128;
    const int n0   = blockIdx.x * 128;
    const int w    = tid >> 5;
    const int lane = tid & 31;
    const int qr   = lane >> 2;     // 0..7
    const int qc   = lane & 3;      // 0..3
    const int wm   = (w & 1) * 64;  // warp m offset in tile
    const int wn   = (w >> 1) * 32; // warp n offset in tile

    const int nt = K >> 5;

    auto copy_stage = [&](int s, int k0) {
        float* da = As + s * SA_STG;
        #pragma unroll
        for (int i = 0; i < 4; i++) {
            int g = tid + 256 * i;
            int r = g >> 3, c = (g & 7) << 2;
            cp_async16(da + r * 36 + c, A + (size_t)(m0 + r) * K + k0 + c);
        }
        float* db = Bs + s * SB;
        if (BT) {
            #pragma unroll
            for (int i = 0; i < 4; i++) {
                int g = tid + 256 * i;
                int r = g >> 3, c = (g & 7) << 2;
                cp_async16(db + r * 36 + c, B + (size_t)(n0 + r) * K + k0 + c);
            }
        } else {
            #pragma unroll
            for (int i = 0; i < 4; i++) {
                int g = tid + 256 * i;
                int r = g >> 5, c = (g & 31) << 2;
                cp_async16(db + r * 136 + c, B + (size_t)(k0 + r) * N + n0 + c);
            }
        }
    };

    float acc[4][4][4];
    #pragma unroll
    for (int mi = 0; mi < 4; mi++)
        #pragma unroll
        for (int nj = 0; nj < 4; nj++)
            #pragma unroll
            for (int r = 0; r < 4; r++) acc[mi][nj][r] = 0.0f;

    copy_stage(0, 0);  cp_commit();
    copy_stage(1, 32); cp_commit();

    for (int t = 0; t < nt; t++) {
        cp_wait<1>();
        __syncthreads();

        const float* a = As + (t & 1) * SA_STG;
        const float* b = Bs + (t & 1) * SB;

        #pragma unroll
        for (int ks = 0; ks < 4; ks++) {
            const int kk = ks * 8;
            uint32_t af[4][4], bf[4][2];
            #pragma unroll
            for (int mi = 0; mi < 4; mi++) {
                const int am = wm + mi * 16;
                af[mi][0] = ldfrag<ACVT>(&a[(am + qr    ) * 36 + kk + qc    ]);
                af[mi][1] = ldfrag<ACVT>(&a[(am + qr + 8) * 36 + kk + qc    ]);
                af[mi][2] = ldfrag<ACVT>(&a[(am + qr    ) * 36 + kk + qc + 4]);
                af[mi][3] = ldfrag<ACVT>(&a[(am + qr + 8) * 36 + kk + qc + 4]);
            }
            #pragma unroll
            for (int nj = 0; nj < 4; nj++) {
                const int bn = wn + nj * 8;
                if (BT) {
                    bf[nj][0] = ldfrag<false>(&b[(bn + qr) * 36 + kk + qc    ]);
                    bf[nj][1] = ldfrag<false>(&b[(bn + qr) * 36 + kk + qc + 4]);
                } else {
                    bf[nj][0] = ldfrag<false>(&b[(kk + qc    ) * 136 + bn + qr]);
                    bf[nj][1] = ldfrag<false>(&b[(kk + qc + 4) * 136 + bn + qr]);
                }
            }
            #pragma unroll
            for (int mi = 0; mi < 4; mi++)
                #pragma unroll
                for (int nj = 0; nj < 4; nj++)
                    mma_tf32(acc[mi][nj], af[mi], bf[nj]);
        }

        __syncthreads();
        if (t + 2 < nt) copy_stage(t & 1, (t + 2) * 32);
        cp_commit();
    }

    // ----- epilogue -----
    float2 bv[4];
    if (HASBIAS) {
        #pragma unroll
        for (int nj = 0; nj < 4; nj++)
            bv[nj] = *(const float2*)&bias[n0 + wn + nj * 8 + qc * 2];
    }
    #pragma unroll
    for (int mi = 0; mi < 4; mi++) {
        const int r0 = m0 + wm + mi * 16 + qr;
        #pragma unroll
        for (int nj = 0; nj < 4; nj++) {
            const int cc = n0 + wn + nj * 8 + qc * 2;
            float2 v0 = make_float2(acc[mi][nj][0], acc[mi][nj][1]);
            float2 v1 = make_float2(acc[mi][nj][2], acc[mi][nj][3]);
            if (HASBIAS) {
                v0.x += bv[nj].x; v0.y += bv[nj].y;
                v1.x += bv[nj].x; v1.y += bv[nj].y;
            }
            if (ADDC) {
                float2 c0 = *(const float2*)&C2[(size_t)r0 * N + cc];
                float2 c1 = *(const float2*)&C2[(size_t)(r0 + 8) * N + cc];
                v0.x += c0.x; v0.y += c0.y;
                v1.x += c1.x; v1.y += c1.y;
            }
            if (RELU) {
                v0.x = fmaxf(v0.x, 0.f); v0.y = fmaxf(v0.y, 0.f);
                v1.x = fmaxf(v1.x, 0.f); v1.y = fmaxf(v1.y, 0.f);
            }
            if (RND) {
                v0.x = roundtf(v0.x); v0.y = roundtf(v0.y);
                v1.x = roundtf(v1.x); v1.y = roundtf(v1.y);
            }
            *(float2*)&C[(size_t)r0 * N + cc]       = v0;
            *(float2*)&C[(size_t)(r0 + 8) * N + cc] = v1;
        }
    }
}

// ---------------------------------------------------------------------------
// Block reduction (256 threads)
// ---------------------------------------------------------------------------
__device__ __forceinline__ float block_sum256(float v)
{
    __shared__ float buf[8];
    int lane = threadIdx.x & 31, wid = threadIdx.x >> 5;
    #pragma unroll
    for (int o = 16; o > 0; o >>= 1) v += __shfl_xor_sync(0xffffffffu, v, o);
    if (lane == 0) buf[wid] = v;
    __syncthreads();
    float r = buf[0] + buf[1] + buf[2] + buf[3] + buf[4] + buf[5] + buf[6] + buf[7];
    __syncthreads();
    return r;
}

// ---------------------------------------------------------------------------
// add + LayerNorm:  x = x1 + x2;  (optionally write rounded x);  out = LN(x)
// RND rounds both pre and out to tf32 (they feed GEMMs as A only).
// ---------------------------------------------------------------------------
template<bool WRITE_PRE, bool RND>
__global__ void __launch_bounds__(256) add_ln_kernel(
    const float* __restrict__ x1, const float* __restrict__ x2,
    const float* __restrict__ gamma, const float* __restrict__ beta,
    float* __restrict__ pre, float* __restrict__ out)
{
    const int n = blockIdx.x;
    const int tid = threadIdx.x;
    const size_t base = (size_t)n * HDIM;

    float4 a = ((const float4*)(x1 + base))[tid];
    float4 c = ((const float4*)(x2 + base))[tid];
    float4 x = make_float4(a.x + c.x, a.y + c.y, a.z + c.z, a.w + c.w);
    if (WRITE_PRE) {
        float4 xp = RND ? make_float4(roundtf(x.x), roundtf(x.y), roundtf(x.z), roundtf(x.w)) : x;
        ((float4*)(pre + base))[tid] = xp;
    }

    float s = x.x + x.y + x.z + x.w;
    s = block_sum256(s);
    const float mu = s * (1.0f / HDIM);

    float d0 = x.x - mu, d1 = x.y - mu, d2 = x.z - mu, d3 = x.w - mu;
    float sq = d0 * d0 + d1 * d1 + d2 * d2 + d3 * d3;
    sq = block_sum256(sq);
    const float rstd = rsqrtf(sq * (1.0f / HDIM) + 1e-12f);

    float4 g4 = ((const float4*)gamma)[tid];
    float4 b4 = ((const float4*)beta)[tid];
    float4 o = make_float4(d0 * rstd * g4.x + b4.x,
                           d1 * rstd * g4.y + b4.y,
                           d2 * rstd * g4.z + b4.z,
                           d3 * rstd * g4.w + b4.w);
    if (RND) o = make_float4(roundtf(o.x), roundtf(o.y), roundtf(o.z), roundtf(o.w));
    ((float4*)(out + base))[tid] = o;
}

// ---------------------------------------------------------------------------
// Round-copy a weight matrix to tf32
// ---------------------------------------------------------------------------
__global__ void round_copy_kernel(const float* __restrict__ in,
                                  float* __restrict__ out, int n)
{
    int i = blockIdx.x * blockDim.x + threadIdx.x;
    int i4 = i << 2;
    if (i4 >= n) return;
    float4 v = *(const float4*)(in + i4);
    *(float4*)(out + i4) = make_float4(roundtf(v.x), roundtf(v.y),
                                       roundtf(v.z), roundtf(v.w));
}

// ---------------------------------------------------------------------------
// uw2[(t*D+d), h] = up_w[t, h, d]; uw2[512+t, h] = up_b[t, h]; rows 520..543 = 0
// (tf32-rounded)
// ---------------------------------------------------------------------------
__global__ void build_uw2_kernel(const float* __restrict__ up_w,
                                 const float* __restrict__ up_b,
                                 float* __restrict__ uw2)
{
    int idx = blockIdx.x * blockDim.x + threadIdx.x;
    if (idx >= TDBP * HDIM) return;
    int j = idx >> 10;          // 0..543
    int h = idx & (HDIM - 1);
    float v = 0.0f;
    if (j < TD) {
        int t = j >> 6, d = j & 63;
        v = up_w[((size_t)t * HDIM + h) * DDIM + d];
    } else if (j < TD + TTASK) {
        v = up_b[(size_t)(j - TD) * HDIM + h];
    }
    uw2[idx] = roundtf(v);
}

// ---------------------------------------------------------------------------
// Scores + softmax over tasks + build pdr (stride TDBP, tf32-rounded).
// ---------------------------------------------------------------------------
__global__ void __launch_bounds__(256) score_softmax_kernel(
    const float* __restrict__ dr, const float* __restrict__ e,
    const float* __restrict__ qk, const float* __restrict__ up_b,
    float* __restrict__ pdr)
{
    const int n = blockIdx.x;
    const int tid = threadIdx.x;
    const int w = tid >> 5, l = tid & 31;

    const size_t b512 = (size_t)n * TD;
    float v = dr[b512 + w * 64 + l]      * e[b512 + w * 64 + l]
            + dr[b512 + w * 64 + 32 + l] * e[b512 + w * 64 + 32 + l];

    const float* qrow = qk + (size_t)n * HDIM;
    const float* ub   = up_b + (size_t)w * HDIM;
    float u = 0.f;
    #pragma unroll 8
    for (int h = l; h < HDIM; h += 32) u += qrow[h] * ub[h];
    v += u;

    #pragma unroll
    for (int o = 16; o > 0; o >>= 1) v += __shfl_xor_sync(0xffffffffu, v, o);

    __shared__ float s[TTASK];
    if (l == 0) s[w] = v;
    __syncthreads();

    float mx = s[0];
    #pragma unroll
    for (int t = 1; t < TTASK; t++) mx = fmaxf(mx, s[t]);
    float p[TTASK]; float sum = 0.f;
    #pragma unroll
    for (int t = 0; t < TTASK; t++) { p[t] = __expf(s[t] - mx); sum += p[t]; }
    const float inv = 1.0f / sum;

    const size_t b = (size_t)n * TDBP;
    #pragma unroll
    for (int r = 0; r < 2; r++) {
        int c = tid + r * 256;              // 0..511
        int t = c >> 6;
        pdr[b + c] = roundtf(p[t] * inv * dr[b512 + c]);
    }
    if (tid < TTASK)       pdr[b + TD + tid] = roundtf(p[tid] * inv);
    else if (tid < 32)     pdr[b + TD + TTASK + (tid - TTASK)] = 0.0f;
}

// ---------------------------------------------------------------------------
// Launch
// ---------------------------------------------------------------------------
struct Scratch {
    float *h, *pre, *ain, *dr, *q, *qk, *e, *pdr, *uw2, *mix, *fus;
    float *dw, *dnw, *qw, *kw, *vw;
};

static constexpr int SMEM_BT1 = 2 * (SA_STG + SB_STG_T) * 4;  // 73728 B
static constexpr int SMEM_BT0 = 2 * (SA_STG + SB_STG_N) * 4;  // 71680 B

static Scratch init_once()
{
    Scratch s;
    cudaGetSymbolAddress((void**)&s.h,   g_h);
    cudaGetSymbolAddress((void**)&s.pre, g_pre);
    cudaGetSymbolAddress((void**)&s.ain, g_ain);
    cudaGetSymbolAddress((void**)&s.dr,  g_dr);
    cudaGetSymbolAddress((void**)&s.q,   g_q);
    cudaGetSymbolAddress((void**)&s.qk,  g_qk);
    cudaGetSymbolAddress((void**)&s.e,   g_e);
    cudaGetSymbolAddress((void**)&s.pdr, g_pdr);
    cudaGetSymbolAddress((void**)&s.uw2, g_uw2);
    cudaGetSymbolAddress((void**)&s.mix, g_mix);
    cudaGetSymbolAddress((void**)&s.fus, g_fus);
    cudaGetSymbolAddress((void**)&s.dw,  g_dw);
    cudaGetSymbolAddress((void**)&s.dnw, g_dnw);
    cudaGetSymbolAddress((void**)&s.qw,  g_qw);
    cudaGetSymbolAddress((void**)&s.kw,  g_kw);
    cudaGetSymbolAddress((void**)&s.vw,  g_vw);
    cudaFuncSetAttribute(gemm_tf32<true,  true,  true,  false, false, false>, cudaFuncAttributeMaxDynamicSharedMemorySize, SMEM_BT1);
    cudaFuncSetAttribute(gemm_tf32<true,  false, true,  true,  false, false>, cudaFuncAttributeMaxDynamicSharedMemorySize, SMEM_BT1);
    cudaFuncSetAttribute(gemm_tf32<true,  false, true,  false, false, true >, cudaFuncAttributeMaxDynamicSharedMemorySize, SMEM_BT1);
    cudaFuncSetAttribute(gemm_tf32<true,  false, false, false, false, false>, cudaFuncAttributeMaxDynamicSharedMemorySize, SMEM_BT1);
    cudaFuncSetAttribute(gemm_tf32<false, false, false, false, false, true >, cudaFuncAttributeMaxDynamicSharedMemorySize, SMEM_BT0);
    cudaFuncSetAttribute(gemm_tf32<false, false, false, false, true,  true >, cudaFuncAttributeMaxDynamicSharedMemorySize, SMEM_BT0);
    return s;
}

extern "C" void kernel_launch(void* const* d_in, const int* in_sizes, int n_in,
                              void* d_out, int out_size)
{
    const float* hs      = (const float*)d_in[0];   // [N, I]
    const float* inp     = (const float*)d_in[1];   // [N, H]
    const float* dense_w = (const float*)d_in[2];   // [H, I]
    const float* dense_b = (const float*)d_in[3];   // [H]
    const float* ln_g    = (const float*)d_in[4];   // [H]
    const float* ln_b    = (const float*)d_in[5];   // [H]
    const float* down_w  = (const float*)d_in[6];   // [T, D, H] -> flat [512, H]
    const float* down_b  = (const float*)d_in[7];   // [T, D]    -> flat [512]
    const float* up_w    = (const float*)d_in[8];   // [T, H, D]
    const float* up_b    = (const float*)d_in[9];   // [T, H]
    const float* key_w   = (const float*)d_in[10];  // [H, H] (key_b cancels)
    const float* query_w = (const float*)d_in[12];  // [H, H]
    const float* query_b = (const float*)d_in[13];  // [H]
    const float* value_w = (const float*)d_in[14];  // [H, H]
    float* out = (float*)d_out;

    static Scratch s = init_once();

    dim3 blk(256);

    // 0. weight prep (tf32 rounding) -- all independent, cheap
    build_uw2_kernel<<<(TDBP * HDIM + 255) / 256, blk>>>(up_w, up_b, s.uw2);
    round_copy_kernel<<<(HDIM * IDIM / 4 + 255) / 256, blk>>>(dense_w, s.dw, HDIM * IDIM);
    round_copy_kernel<<<(TD * HDIM / 4 + 255) / 256, blk>>>(down_w, s.dnw, TD * HDIM);
    round_copy_kernel<<<(HDIM * HDIM / 4 + 255) / 256, blk>>>(query_w, s.qw, HDIM * HDIM);
    round_copy_kernel<<<(HDIM * HDIM / 4 + 255) / 256, blk>>>(key_w, s.kw, HDIM * HDIM);
    round_copy_kernel<<<(HDIM * HDIM / 4 + 255) / 256, blk>>>(value_w, s.vw, HDIM * HDIM);

    // 1. h = hs @ dense_w^T + dense_b          [N,H], K=I   (A cvt in-loop)
    gemm_tf32<true, true, true, false, false, false><<<dim3(HDIM / 128, NTOK / 128), blk, SMEM_BT1>>>(
        hs, s.dw, dense_b, nullptr, s.h, NTOK, HDIM, IDIM);

    // 2. pre = round(inp + h); ain = round(LN(pre))
    add_ln_kernel<true, true><<<NTOK, blk>>>(inp, s.h, ln_g, ln_b, s.pre, s.ain);

    // 3. dr = relu(ain @ down_w^T + down_b)    [N,512], K=H
    gemm_tf32<true, false, true, true, false, false><<<dim3(TD / 128, NTOK / 128), blk, SMEM_BT1>>>(
        s.ain, s.dnw, down_b, nullptr, s.dr, NTOK, TD, HDIM);

    // 4. q = round(pre @ query_w^T + query_b)  [N,H], K=H
    gemm_tf32<true, false, true, false, false, true><<<dim3(HDIM / 128, NTOK / 128), blk, SMEM_BT1>>>(
        s.pre, s.qw, query_b, nullptr, s.q, NTOK, HDIM, HDIM);

    // 5. qk = round(q @ key_w)                 [N,H], K=H
    gemm_tf32<false, false, false, false, false, true><<<dim3(HDIM / 128, NTOK / 128), blk, SMEM_BT0>>>(
        s.q, s.kw, nullptr, nullptr, s.qk, NTOK, HDIM, HDIM);

    // 6. e = qk @ uw2[0:512]^T                 [N,512], K=H
    gemm_tf32<true, false, false, false, false, false><<<dim3(TD / 128, NTOK / 128), blk, SMEM_BT1>>>(
        s.qk, s.uw2, nullptr, nullptr, s.e, NTOK, TD, HDIM);

    // 7. scores + softmax + pdr (rounded)
    score_softmax_kernel<<<NTOK, blk>>>(s.dr, s.e, s.qk, up_b, s.pdr);

    // 8. mix = round(pdr @ uw2 + h)            [N,H], K=544
    gemm_tf32<false, false, false, false, true, true><<<dim3(HDIM / 128, NTOK / 128), blk, SMEM_BT0>>>(
        s.pdr, s.uw2, nullptr, s.h, s.mix, NTOK, HDIM, TDBP);

    // 9. fus = mix @ value_w^T                 [N,H], K=H
    gemm_tf32<true, false, false, false, false, false><<<dim3(HDIM / 128, NTOK / 128), blk, SMEM_BT1>>>(
        s.mix, s.vw, nullptr, nullptr, s.fus, NTOK, HDIM, HDIM);

    // 10. out = LN(inp + fus)
    add_ln_kernel<false, false><<<NTOK, blk>>>(inp, s.fus, ln_g, ln_b, nullptr, out);
}

// round 7
// speedup vs baseline: 4.2688x; 1.2945x over previous
#include <cuda_runtime.h>
#include <cuda_fp16.h>
#include <stdint.h>

// ---------------------------------------------------------------------------
// Problem constants
// ---------------------------------------------------------------------------
#define NTOK 4096          // B*S
#define HDIM 1024          // hidden
#define IDIM 4096          // intermediate
#define TTASK 8            // tasks
#define TD 512             // T*D
#define TDBP 576           // T*D + T, padded to multiple of 64

// ---------------------------------------------------------------------------
// Scratch (static device globals; no allocation allowed)
// ---------------------------------------------------------------------------
__device__ __align__(16) __half g_hsh[NTOK * IDIM];   // hs in fp16
__device__ float  g_h  [NTOK * HDIM];                 // dense out (fp32 residual)
__device__ __align__(16) __half g_pre[NTOK * HDIM];
__device__ __align__(16) __half g_ain[NTOK * HDIM];
__device__ __align__(16) __half g_dr [NTOK * TD];
__device__ __align__(16) __half g_q  [NTOK * HDIM];
__device__ __align__(16) __half g_qk [NTOK * HDIM];
__device__ __align__(16) __half g_e  [NTOK * TD];
__device__ __align__(16) __half g_pdr[NTOK * TDBP];
__device__ __align__(16) __half g_mix[NTOK * HDIM];
__device__ float  g_fus[NTOK * HDIM];
// fp16 weights, all [N, K] row-major
__device__ __align__(16) __half g_dw  [HDIM * IDIM];  // dense_w
__device__ __align__(16) __half g_dnw [TD * HDIM];    // down_w
__device__ __align__(16) __half g_qw  [HDIM * HDIM];  // query_w
__device__ __align__(16) __half g_kwT [HDIM * HDIM];  // key_w^T
__device__ __align__(16) __half g_vw  [HDIM * HDIM];  // value_w
__device__ __align__(16) __half g_uw2 [TD * HDIM];    // up_w^T  [j=t*64+d][h]
__device__ __align__(16) __half g_uw2T[HDIM * TDBP];  // [h][j] (+up_b col 512..519, pad 0)

// ---------------------------------------------------------------------------
// PTX helpers
// ---------------------------------------------------------------------------
__device__ __forceinline__ uint32_t smem_u32(const void* p) {
    uint32_t a;
    asm("{ .reg .u64 t; cvta.to.shared.u64 t, %1; cvt.u32.u64 %0, t; }" : "=r"(a) : "l"(p));
    return a;
}
__device__ __forceinline__ void cp_async16(uint32_t smem, const void* gmem) {
    asm volatile("cp.async.cg.shared.global [%0], [%1], 16;\n" :: "r"(smem), "l"(gmem));
}
__device__ __forceinline__ void cp_commit() {
    asm volatile("cp.async.commit_group;\n");
}
template<int W> __device__ __forceinline__ void cp_wait() {
    asm volatile("cp.async.wait_group %0;\n" :: "n"(W));
}
__device__ __forceinline__ uint32_t sw128(uint32_t off) {   // SW128 swizzle
    return off ^ ((off >> 3) & 0x70);
}
__device__ __forceinline__ void ldsm4(uint32_t* d, uint32_t addr) {
    asm volatile("ldmatrix.sync.aligned.m8n8.x4.shared.b16 {%0,%1,%2,%3}, [%4];"
        : "=r"(d[0]), "=r"(d[1]), "=r"(d[2]), "=r"(d[3]) : "r"(addr));
}
__device__ __forceinline__ void mma_f16(float* c, const uint32_t* a, const uint32_t* b) {
    asm volatile("mma.sync.aligned.m16n8k16.row.col.f32.f16.f16.f32 "
        "{%0,%1,%2,%3}, {%4,%5,%6,%7}, {%8,%9}, {%0,%1,%2,%3};"
        : "+f"(c[0]), "+f"(c[1]), "+f"(c[2]), "+f"(c[3])
        : "r"(a[0]), "r"(a[1]), "r"(a[2]), "r"(a[3]), "r"(b[0]), "r"(b[1]));
}

// ---------------------------------------------------------------------------
// fp16 HMMA GEMM: C[M,N] = A[M,K](fp16) @ B[N,K](fp16)^T (+bias)(relu)(+C2)
// CTA 128x128, BK=64 halfs (128B SW128 rows), 256 thr (8 warps 2x4, 64x32/warp),
// 3-stage cp.async, ldmatrix fragments, fp32 accum. 2 CTAs/SM.
// Requires M%128==0, N%128==0, K%64==0, K/64 >= 3.
// ---------------------------------------------------------------------------
template<bool HASBIAS, bool RELU, bool ADDC, bool OUTHALF>
__global__ void __launch_bounds__(256, 2) gemm_h(
    const __half* __restrict__ A, const __half* __restrict__ B,
    const float* __restrict__ bias, const float* __restrict__ C2,
    void* __restrict__ Cv, int N, int K)
{
    constexpr int STAGES = 3;
    constexpr int STG = 128 * 128;              // bytes per matrix stage
    extern __shared__ __align__(1024) char smem[];
    const uint32_t sb  = smem_u32(smem);
    const uint32_t SA  = sb;
    const uint32_t SBB = sb + STAGES * STG;

    const int tid = threadIdx.x, w = tid >> 5, lane = tid & 31;
    const int m0 = blockIdx.y * 128, n0 = blockIdx.x * 128;
    const int wm = (w & 1) * 64, wn = (w >> 1) * 32;
    const int qr = lane >> 2, qc = lane & 3;
    const int nt = K >> 6;

    auto copy_stage = [&](int s, int k0 /*halfs*/) {
        #pragma unroll
        for (int i = 0; i < 4; i++) {
            int g = tid + 256 * i;
            int r = g >> 3, cb = (g & 7) << 4;
            cp_async16(SA + s * STG + sw128(r * 128 + cb),
                       A + (size_t)(m0 + r) * K + k0 + (cb >> 1));
        }
        #pragma unroll
        for (int i = 0; i < 4; i++) {
            int g = tid + 256 * i;
            int r = g >> 3, cb = (g & 7) << 4;
            cp_async16(SBB + s * STG + sw128(r * 128 + cb),
                       B + (size_t)(n0 + r) * K + k0 + (cb >> 1));
        }
    };

    float acc[4][4][4];
    #pragma unroll
    for (int mi = 0; mi < 4; mi++)
        #pragma unroll
        for (int nj = 0; nj < 4; nj++)
            #pragma unroll
            for (int r = 0; r < 4; r++) acc[mi][nj][r] = 0.0f;

    copy_stage(0, 0);   cp_commit();
    copy_stage(1, 64);  cp_commit();
    copy_stage(2, 128); cp_commit();

    // lane-constant fragment address components
    const int a_r  = lane & 15;
    const int a_cb = (lane >> 4) << 4;            // 0 | 16
    const int b_r  = ((lane >> 4) & 1) * 8 + (lane & 7);
    const int b_cb = ((lane >> 3) & 1) << 4;      // 0 | 16

    for (int t = 0; t < nt; t++) {
        cp_wait<STAGES - 1>();
        __syncthreads();
        const uint32_t aB = SA  + (t % 3) * STG;
        const uint32_t bB = SBB + (t % 3) * STG;

        #pragma unroll
        for (int kc = 0; kc < 4; kc++) {
            const int kb = kc * 32;               // byte col base (16 halfs)
            uint32_t bf[8];
            #pragma unroll
            for (int h = 0; h < 2; h++) {         // nj pairs {0,1}, {2,3}
                int r = wn + h * 16 + b_r;
                ldsm4(&bf[h * 4], bB + sw128(r * 128 + kb + b_cb));
            }
            #pragma unroll
            for (int mi = 0; mi < 4; mi++) {
                int r = wm + mi * 16 + a_r;
                uint32_t af[4];
                ldsm4(af, aB + sw128(r * 128 + kb + a_cb));
                #pragma unroll
                for (int nj = 0; nj < 4; nj++)
                    mma_f16(acc[mi][nj], af, &bf[nj * 2]);
            }
        }

        __syncthreads();
        if (t + STAGES < nt) copy_stage(t % 3, (t + STAGES) * 64);
        cp_commit();
    }

    // ----- epilogue -----
    float2 bv[4];
    if (HASBIAS) {
        #pragma unroll
        for (int nj = 0; nj < 4; nj++)
            bv[nj] = *(const float2*)&bias[n0 + wn + nj * 8 + qc * 2];
    }
    #pragma unroll
    for (int mi = 0; mi < 4; mi++) {
        const int r0 = m0 + wm + mi * 16 + qr;
        #pragma unroll
        for (int nj = 0; nj < 4; nj++) {
            const int cc = n0 + wn + nj * 8 + qc * 2;
            float2 v0 = make_float2(acc[mi][nj][0], acc[mi][nj][1]);
            float2 v1 = make_float2(acc[mi][nj][2], acc[mi][nj][3]);
            if (HASBIAS) {
                v0.x += bv[nj].x; v0.y += bv[nj].y;
                v1.x += bv[nj].x; v1.y += bv[nj].y;
            }
            if (ADDC) {
                float2 c0 = *(const float2*)&C2[(size_t)r0 * N + cc];
                float2 c1 = *(const float2*)&C2[(size_t)(r0 + 8) * N + cc];
                v0.x += c0.x; v0.y += c0.y;
                v1.x += c1.x; v1.y += c1.y;
            }
            if (RELU) {
                v0.x = fmaxf(v0.x, 0.f); v0.y = fmaxf(v0.y, 0.f);
                v1.x = fmaxf(v1.x, 0.f); v1.y = fmaxf(v1.y, 0.f);
            }
            if (OUTHALF) {
                __half* C = (__half*)Cv;
                *(__half2*)&C[(size_t)r0 * N + cc]       = __floats2half2_rn(v0.x, v0.y);
                *(__half2*)&C[(size_t)(r0 + 8) * N + cc] = __floats2half2_rn(v1.x, v1.y);
            } else {
                float* C = (float*)Cv;
                *(float2*)&C[(size_t)r0 * N + cc]       = v0;
                *(float2*)&C[(size_t)(r0 + 8) * N + cc] = v1;
            }
        }
    }
}

// ---------------------------------------------------------------------------
// Block reduction (256 threads)
// ---------------------------------------------------------------------------
__device__ __forceinline__ float block_sum256(float v)
{
    __shared__ float buf[8];
    int lane = threadIdx.x & 31, wid = threadIdx.x >> 5;
    #pragma unroll
    for (int o = 16; o > 0; o >>= 1) v += __shfl_xor_sync(0xffffffffu, v, o);
    if (lane == 0) buf[wid] = v;
    __syncthreads();
    float r = buf[0] + buf[1] + buf[2] + buf[3] + buf[4] + buf[5] + buf[6] + buf[7];
    __syncthreads();
    return r;
}

// ---------------------------------------------------------------------------
// add + LayerNorm: x = x1 + x2; optionally write fp16 x; out = LN(x) (fp16|fp32)
// ---------------------------------------------------------------------------
template<bool WRITE_PRE, bool OUTHALF>
__global__ void __launch_bounds__(256) add_ln_kernel(
    const float* __restrict__ x1, const float* __restrict__ x2,
    const float* __restrict__ gamma, const float* __restrict__ beta,
    __half* __restrict__ pre, void* __restrict__ out)
{
    const int n = blockIdx.x;
    const int tid = threadIdx.x;
    const size_t base = (size_t)n * HDIM;

    float4 a = ((const float4*)(x1 + base))[tid];
    float4 c = ((const float4*)(x2 + base))[tid];
    float4 x = make_float4(a.x + c.x, a.y + c.y, a.z + c.z, a.w + c.w);
    if (WRITE_PRE) {
        __half2* p = (__half2*)(pre + base) + tid * 2;
        p[0] = __floats2half2_rn(x.x, x.y);
        p[1] = __floats2half2_rn(x.z, x.w);
    }

    float s = x.x + x.y + x.z + x.w;
    s = block_sum256(s);
    const float mu = s * (1.0f / HDIM);

    float d0 = x.x - mu, d1 = x.y - mu, d2 = x.z - mu, d3 = x.w - mu;
    float sq = d0 * d0 + d1 * d1 + d2 * d2 + d3 * d3;
    sq = block_sum256(sq);
    const float rstd = rsqrtf(sq * (1.0f / HDIM) + 1e-12f);

    float4 g4 = ((const float4*)gamma)[tid];
    float4 b4 = ((const float4*)beta)[tid];
    float o0 = d0 * rstd * g4.x + b4.x;
    float o1 = d1 * rstd * g4.y + b4.y;
    float o2 = d2 * rstd * g4.z + b4.z;
    float o3 = d3 * rstd * g4.w + b4.w;
    if (OUTHALF) {
        __half2* p = (__half2*)((__half*)out + base) + tid * 2;
        p[0] = __floats2half2_rn(o0, o1);
        p[1] = __floats2half2_rn(o2, o3);
    } else {
        ((float4*)((float*)out + base))[tid] = make_float4(o0, o1, o2, o3);
    }
}

// ---------------------------------------------------------------------------
// Prep kernels
// ---------------------------------------------------------------------------
__global__ void half_copy_kernel(const float* __restrict__ in,
                                 __half* __restrict__ out, int n)
{
    int i4 = (blockIdx.x * blockDim.x + threadIdx.x) << 2;
    if (i4 >= n) return;
    float4 v = *(const float4*)(in + i4);
    __half2* o = (__half2*)(out + i4);
    o[0] = __floats2half2_rn(v.x, v.y);
    o[1] = __floats2half2_rn(v.z, v.w);
}

__global__ void transpose_half_kernel(const float* __restrict__ in,   // [H,H]
                                      __half* __restrict__ out)       // out[n][k]=in[k][n]
{
    int idx = blockIdx.x * blockDim.x + threadIdx.x;
    if (idx >= HDIM * HDIM) return;
    int nR = idx >> 10, k = idx & (HDIM - 1);
    out[idx] = __float2half_rn(in[(size_t)k * HDIM + nR]);
}

// uw2[j][h] = up_w[t,h,d]   (j = t*64+d)          [512 x 1024]
__global__ void build_uw2_kernel(const float* __restrict__ up_w,
                                 __half* __restrict__ uw2)
{
    int idx = blockIdx.x * blockDim.x + threadIdx.x;
    if (idx >= TD * HDIM) return;
    int j = idx >> 10, h = idx & (HDIM - 1);
    int t = j >> 6, d = j & 63;
    uw2[idx] = __float2half_rn(up_w[((size_t)t * HDIM + h) * 64 + d]);
}

// uw2T[h][j]: j<512 -> up_w[t,h,d]; 512..519 -> up_b[j-512][h]; else 0  [1024 x 576]
__global__ void build_uw2T_kernel(const float* __restrict__ up_w,
                                  const float* __restrict__ up_b,
                                  __half* __restrict__ uw2T)
{
    int idx = blockIdx.x * blockDim.x + threadIdx.x;
    if (idx >= HDIM * TDBP) return;
    int h = idx / TDBP, j = idx % TDBP;
    float v = 0.0f;
    if (j < TD) {
        int t = j >> 6, d = j & 63;
        v = up_w[((size_t)t * HDIM + h) * 64 + d];
    } else if (j < TD + TTASK) {
        v = up_b[(size_t)(j - TD) * HDIM + h];
    }
    uw2T[idx] = __float2half_rn(v);
}

// ---------------------------------------------------------------------------
// Scores + softmax over tasks + pdr (fp16, stride TDBP, pad zeroed)
//   s[t] = sum_d dr*e + sum_h qk*up_b[t]   (query.key_b cancels in softmax)
// ---------------------------------------------------------------------------
__global__ void __launch_bounds__(256) score_softmax_kernel(
    const __half* __restrict__ dr, const __half* __restrict__ e,
    const __half* __restrict__ qk, const float* __restrict__ up_b,
    __half* __restrict__ pdr)
{
    const int n = blockIdx.x;
    const int tid = threadIdx.x;
    const int w = tid >> 5, l = tid & 31;

    const size_t b512 = (size_t)n * TD;
    float v = __half2float(dr[b512 + w * 64 + l])      * __half2float(e[b512 + w * 64 + l])
            + __half2float(dr[b512 + w * 64 + 32 + l]) * __half2float(e[b512 + w * 64 + 32 + l]);

    const __half* qrow = qk + (size_t)n * HDIM;
    const float* ub = up_b + (size_t)w * HDIM;
    float u = 0.f;
    #pragma unroll 8
    for (int h = l; h < HDIM; h += 32) u += __half2float(qrow[h]) * ub[h];
    v += u;

    #pragma unroll
    for (int o = 16; o > 0; o >>= 1) v += __shfl_xor_sync(0xffffffffu, v, o);

    __shared__ float s[TTASK];
    if (l == 0) s[w] = v;
    __syncthreads();

    float mx = s[0];
    #pragma unroll
    for (int t = 1; t < TTASK; t++) mx = fmaxf(mx, s[t]);
    float p[TTASK]; float sum = 0.f;
    #pragma unroll
    for (int t = 0; t < TTASK; t++) { p[t] = __expf(s[t] - mx); sum += p[t]; }
    const float inv = 1.0f / sum;

    const size_t b = (size_t)n * TDBP;
    #pragma unroll
    for (int r = 0; r < 2; r++) {
        int c = tid + r * 256;
        int t = c >> 6;
        pdr[b + c] = __float2half_rn(p[t] * inv * __half2float(dr[b512 + c]));
    }
    if (tid < TTASK)   pdr[b + TD + tid] = __float2half_rn(p[tid] * inv);
    else if (tid < 64) pdr[b + TD + tid] = __float2half_rn(0.0f);   // cols 520..575
}

// ---------------------------------------------------------------------------
// Launch
// ---------------------------------------------------------------------------
struct Scratch {
    __half *hsh, *pre, *ain, *dr, *q, *qk, *e, *pdr, *mix;
    __half *dw, *dnw, *qw, *kwT, *vw, *uw2, *uw2T;
    float *h, *fus;
};

static constexpr int SMEM_H = 3 * 2 * 16384;   // 98304 B

static Scratch init_once()
{
    Scratch s;
    cudaGetSymbolAddress((void**)&s.hsh,  g_hsh);
    cudaGetSymbolAddress((void**)&s.pre,  g_pre);
    cudaGetSymbolAddress((void**)&s.ain,  g_ain);
    cudaGetSymbolAddress((void**)&s.dr,   g_dr);
    cudaGetSymbolAddress((void**)&s.q,    g_q);
    cudaGetSymbolAddress((void**)&s.qk,   g_qk);
    cudaGetSymbolAddress((void**)&s.e,    g_e);
    cudaGetSymbolAddress((void**)&s.pdr,  g_pdr);
    cudaGetSymbolAddress((void**)&s.mix,  g_mix);
    cudaGetSymbolAddress((void**)&s.dw,   g_dw);
    cudaGetSymbolAddress((void**)&s.dnw,  g_dnw);
    cudaGetSymbolAddress((void**)&s.qw,   g_qw);
    cudaGetSymbolAddress((void**)&s.kwT,  g_kwT);
    cudaGetSymbolAddress((void**)&s.vw,   g_vw);
    cudaGetSymbolAddress((void**)&s.uw2,  g_uw2);
    cudaGetSymbolAddress((void**)&s.uw2T, g_uw2T);
    cudaGetSymbolAddress((void**)&s.h,    g_h);
    cudaGetSymbolAddress((void**)&s.fus,  g_fus);
    cudaFuncSetAttribute(gemm_h<true,  false, false, false>, cudaFuncAttributeMaxDynamicSharedMemorySize, SMEM_H);
    cudaFuncSetAttribute(gemm_h<true,  true,  false, true >, cudaFuncAttributeMaxDynamicSharedMemorySize, SMEM_H);
    cudaFuncSetAttribute(gemm_h<true,  false, false, true >, cudaFuncAttributeMaxDynamicSharedMemorySize, SMEM_H);
    cudaFuncSetAttribute(gemm_h<false, false, false, true >, cudaFuncAttributeMaxDynamicSharedMemorySize, SMEM_H);
    cudaFuncSetAttribute(gemm_h<false, false, true,  true >, cudaFuncAttributeMaxDynamicSharedMemorySize, SMEM_H);
    cudaFuncSetAttribute(gemm_h<false, false, false, false>, cudaFuncAttributeMaxDynamicSharedMemorySize, SMEM_H);
    return s;
}

extern "C" void kernel_launch(void* const* d_in, const int* in_sizes, int n_in,
                              void* d_out, int out_size)
{
    const float* hs      = (const float*)d_in[0];
    const float* inp     = (const float*)d_in[1];
    const float* dense_w = (const float*)d_in[2];
    const float* dense_b = (const float*)d_in[3];
    const float* ln_g    = (const float*)d_in[4];
    const float* ln_b    = (const float*)d_in[5];
    const float* down_w  = (const float*)d_in[6];
    const float* down_b  = (const float*)d_in[7];
    const float* up_w    = (const float*)d_in[8];
    const float* up_b    = (const float*)d_in[9];
    const float* key_w   = (const float*)d_in[10];  // key_b cancels in softmax
    const float* query_w = (const float*)d_in[12];
    const float* query_b = (const float*)d_in[13];
    const float* value_w = (const float*)d_in[14];
    float* out = (float*)d_out;

    static Scratch s = init_once();

    dim3 blk(256);

    // 0. fp16 conversions / layouts
    half_copy_kernel<<<NTOK * IDIM / 4 / 256, blk>>>(hs, s.hsh, NTOK * IDIM);
    half_copy_kernel<<<HDIM * IDIM / 4 / 256, blk>>>(dense_w, s.dw, HDIM * IDIM);
    half_copy_kernel<<<TD * HDIM / 4 / 256, blk>>>(down_w, s.dnw, TD * HDIM);
    half_copy_kernel<<<HDIM * HDIM / 4 / 256, blk>>>(query_w, s.qw, HDIM * HDIM);
    half_copy_kernel<<<HDIM * HDIM / 4 / 256, blk>>>(value_w, s.vw, HDIM * HDIM);
    transpose_half_kernel<<<HDIM * HDIM / 256, blk>>>(key_w, s.kwT);
    build_uw2_kernel<<<TD * HDIM / 256, blk>>>(up_w, s.uw2);
    build_uw2T_kernel<<<(HDIM * TDBP + 255) / 256, blk>>>(up_w, up_b, s.uw2T);

    // 1. h = hs @ dense_w^T + dense_b            [4096,1024], K=4096 (fp32 out)
    gemm_h<true, false, false, false><<<dim3(8, 32), blk, SMEM_H>>>(
        s.hsh, s.dw, dense_b, nullptr, s.h, HDIM, IDIM);

    // 2. pre = h16(inp + h); ain = h16(LN(.))
    add_ln_kernel<true, true><<<NTOK, blk>>>(inp, s.h, ln_g, ln_b, s.pre, s.ain);

    // 3. dr = relu(ain @ down_w^T + down_b)      [4096,512], K=1024
    gemm_h<true, true, false, true><<<dim3(4, 32), blk, SMEM_H>>>(
        s.ain, s.dnw, down_b, nullptr, s.dr, TD, HDIM);

    // 4. q = pre @ query_w^T + query_b           [4096,1024], K=1024
    gemm_h<true, false, false, true><<<dim3(8, 32), blk, SMEM_H>>>(
        s.pre, s.qw, query_b, nullptr, s.q, HDIM, HDIM);

    // 5. qk = q @ key_w = q @ kwT^T              [4096,1024], K=1024
    gemm_h<false, false, false, true><<<dim3(8, 32), blk, SMEM_H>>>(
        s.q, s.kwT, nullptr, nullptr, s.qk, HDIM, HDIM);

    // 6. e = qk @ uw2^T                          [4096,512], K=1024
    gemm_h<false, false, false, true><<<dim3(4, 32), blk, SMEM_H>>>(
        s.qk, s.uw2, nullptr, nullptr, s.e, TD, HDIM);

    // 7. scores + softmax + pdr
    score_softmax_kernel<<<NTOK, blk>>>(s.dr, s.e, s.qk, up_b, s.pdr);

    // 8. mix = pdr @ uw2T^T + h                  [4096,1024], K=576
    gemm_h<false, false, true, true><<<dim3(8, 32), blk, SMEM_H>>>(
        s.pdr, s.uw2T, nullptr, s.h, s.mix, HDIM, TDBP);

    // 9. fus = mix @ value_w^T                   [4096,1024], K=1024 (fp32 out)
    gemm_h<false, false, false, false><<<dim3(8, 32), blk, SMEM_H>>>(
        s.mix, s.vw, nullptr, nullptr, s.fus, HDIM, HDIM);

    // 10. out = LN(inp + fus)
    add_ln_kernel<false, false><<<NTOK, blk>>>(inp, s.fus, ln_g, ln_b, nullptr, out);
}

// round 8
// speedup vs baseline: 6.0120x; 1.4083x over previous
#include <cuda_runtime.h>
#include <cuda_fp16.h>
#include <stdint.h>

// ---------------------------------------------------------------------------
// Problem constants
// ---------------------------------------------------------------------------
#define NTOK 4096          // B*S
#define HDIM 1024          // hidden
#define IDIM 4096          // intermediate
#define TTASK 8            // tasks
#define TD 512             // T*D
#define TDBP 576           // T*D + T, padded to multiple of 64

// ---------------------------------------------------------------------------
// Scratch (static device globals; no allocation allowed)
// ---------------------------------------------------------------------------
__device__ __align__(16) __half g_hsh[NTOK * IDIM];   // hs in fp16
__device__ float  g_h  [NTOK * HDIM];                 // dense out (fp32 residual)
__device__ __align__(16) __half g_pre[NTOK * HDIM];
__device__ __align__(16) __half g_ain[NTOK * HDIM];
__device__ __align__(16) __half g_dr [NTOK * TD];
__device__ __align__(16) __half g_qk [NTOK * HDIM];
__device__ __align__(16) __half g_e  [NTOK * TD];
__device__ __align__(16) __half g_pdr[NTOK * TDBP];
__device__ __align__(16) __half g_mix[NTOK * HDIM];
__device__ float  g_fus[NTOK * HDIM];
// fp16 weights, all [N, K] row-major
__device__ __align__(16) __half g_dw  [HDIM * IDIM];  // dense_w
__device__ __align__(16) __half g_dnw [TD * HDIM];    // down_w
__device__ __align__(16) __half g_qwT [HDIM * HDIM];  // query_w^T
__device__ __align__(16) __half g_kwT [HDIM * HDIM];  // key_w^T
__device__ __align__(16) __half g_wqk [HDIM * HDIM];  // W_qk = Qw^T Kw, rows = out dim
__device__ __align__(16) __half g_vw  [HDIM * HDIM];  // value_w
__device__ __align__(16) __half g_uw2 [TD * HDIM];    // up_w^T  [j=t*64+d][h]
__device__ __align__(16) __half g_uw2T[HDIM * TDBP];  // [h][j] (+up_b col 512..519, pad 0)
__device__ float g_qkb[HDIM];                         // query_b @ key_w

// ---------------------------------------------------------------------------
// PTX helpers
// ---------------------------------------------------------------------------
__device__ __forceinline__ uint32_t smem_u32(const void* p) {
    uint32_t a;
    asm("{ .reg .u64 t; cvta.to.shared.u64 t, %1; cvt.u32.u64 %0, t; }" : "=r"(a) : "l"(p));
    return a;
}
__device__ __forceinline__ void cp_async16(uint32_t smem, const void* gmem) {
    asm volatile("cp.async.cg.shared.global [%0], [%1], 16;\n" :: "r"(smem), "l"(gmem));
}
__device__ __forceinline__ void cp_commit() {
    asm volatile("cp.async.commit_group;\n");
}
template<int W> __device__ __forceinline__ void cp_wait() {
    asm volatile("cp.async.wait_group %0;\n" :: "n"(W));
}
__device__ __forceinline__ uint32_t sw128(uint32_t off) {   // SW128 swizzle
    return off ^ ((off >> 3) & 0x70);
}
__device__ __forceinline__ void ldsm4(uint32_t* d, uint32_t addr) {
    asm volatile("ldmatrix.sync.aligned.m8n8.x4.shared.b16 {%0,%1,%2,%3}, [%4];"
        : "=r"(d[0]), "=r"(d[1]), "=r"(d[2]), "=r"(d[3]) : "r"(addr));
}
__device__ __forceinline__ void mma_f16(float* c, const uint32_t* a, const uint32_t* b) {
    asm volatile("mma.sync.aligned.m16n8k16.row.col.f32.f16.f16.f32 "
        "{%0,%1,%2,%3}, {%4,%5,%6,%7}, {%8,%9}, {%0,%1,%2,%3};"
        : "+f"(c[0]), "+f"(c[1]), "+f"(c[2]), "+f"(c[3])
        : "r"(a[0]), "r"(a[1]), "r"(a[2]), "r"(a[3]), "r"(b[0]), "r"(b[1]));
}

// ---------------------------------------------------------------------------
// fp16 HMMA GEMM: C[M,N] = A[M,K](fp16) @ B[N,K](fp16)^T (+bias)(relu)(+C2)
// CTA tile MT x 128 (MT = 128 or 64), BK=64 halfs (128B SW128 rows), 256 thr,
// 8 warps (2 m x 4 n), warp tile (MT/2) x 32. 3-stage cp.async, ldmatrix,
// fp32 accum, 2 CTAs/SM. Requires M%MT==0, N%128==0, K%64==0, K/64 >= 3.
// ---------------------------------------------------------------------------
template<int MT, bool HASBIAS, bool RELU, bool ADDC, bool OUTHALF>
__global__ void __launch_bounds__(256, 2) gemm_h(
    const __half* __restrict__ A, const __half* __restrict__ B,
    const float* __restrict__ bias, const float* __restrict__ C2,
    void* __restrict__ Cv, int N, int K)
{
    constexpr int STAGES = 3;
    constexpr int ASTG = MT * 128;              // bytes per A stage
    constexpr int BSTG = 128 * 128;             // bytes per B stage
    constexpr int MI = MT / 32;                 // 16-row m-subtiles per warp
    extern __shared__ __align__(1024) char smem[];
    const uint32_t sb  = smem_u32(smem);
    const uint32_t SA  = sb;
    const uint32_t SBB = sb + STAGES * ASTG;

    const int tid = threadIdx.x, w = tid >> 5, lane = tid & 31;
    const int m0 = blockIdx.y * MT, n0 = blockIdx.x * 128;
    const int wm = (w & 1) * (MT / 2), wn = (w >> 1) * 32;
    const int qr = lane >> 2, qc = lane & 3;
    const int nt = K >> 6;

    auto copy_stage = [&](int s, int k0 /*halfs*/) {
        #pragma unroll
        for (int i = 0; i < MT / 32; i++) {
            int g = tid + 256 * i;
            int r = g >> 3, cb = (g & 7) << 4;
            cp_async16(SA + s * ASTG + sw128(r * 128 + cb),
                       A + (size_t)(m0 + r) * K + k0 + (cb >> 1));
        }
        #pragma unroll
        for (int i = 0; i < 4; i++) {
            int g = tid + 256 * i;
            int r = g >> 3, cb = (g & 7) << 4;
            cp_async16(SBB + s * BSTG + sw128(r * 128 + cb),
                       B + (size_t)(n0 + r) * K + k0 + (cb >> 1));
        }
    };

    float acc[MI][4][4];
    #pragma unroll
    for (int mi = 0; mi < MI; mi++)
        #pragma unroll
        for (int nj = 0; nj < 4; nj++)
            #pragma unroll
            for (int r = 0; r < 4; r++) acc[mi][nj][r] = 0.0f;

    copy_stage(0, 0);   cp_commit();
    copy_stage(1, 64);  cp_commit();
    copy_stage(2, 128); cp_commit();

    const int a_r  = lane & 15;
    const int a_cb = (lane >> 4) << 4;            // 0 | 16
    const int b_r  = ((lane >> 4) & 1) * 8 + (lane & 7);
    const int b_cb = ((lane >> 3) & 1) << 4;      // 0 | 16

    for (int t = 0; t < nt; t++) {
        cp_wait<STAGES - 1>();
        __syncthreads();
        const uint32_t aB = SA  + (t % 3) * ASTG;
        const uint32_t bB = SBB + (t % 3) * BSTG;

        #pragma unroll
        for (int kc = 0; kc < 4; kc++) {
            const int kb = kc * 32;               // byte col base (16 halfs)
            uint32_t bf[8];
            #pragma unroll
            for (int h = 0; h < 2; h++) {
                int r = wn + h * 16 + b_r;
                ldsm4(&bf[h * 4], bB + sw128(r * 128 + kb + b_cb));
            }
            #pragma unroll
            for (int mi = 0; mi < MI; mi++) {
                int r = wm + mi * 16 + a_r;
                uint32_t af[4];
                ldsm4(af, aB + sw128(r * 128 + kb + a_cb));
                #pragma unroll
                for (int nj = 0; nj < 4; nj++)
                    mma_f16(acc[mi][nj], af, &bf[nj * 2]);
            }
        }

        __syncthreads();
        if (t + STAGES < nt) copy_stage(t % 3, (t + STAGES) * 64);
        cp_commit();
    }

    // ----- epilogue -----
    float2 bv[4];
    if (HASBIAS) {
        #pragma unroll
        for (int nj = 0; nj < 4; nj++)
            bv[nj] = *(const float2*)&bias[n0 + wn + nj * 8 + qc * 2];
    }
    #pragma unroll
    for (int mi = 0; mi < MI; mi++) {
        const int r0 = m0 + wm + mi * 16 + qr;
        #pragma unroll
        for (int nj = 0; nj < 4; nj++) {
            const int cc = n0 + wn + nj * 8 + qc * 2;
            float2 v0 = make_float2(acc[mi][nj][0], acc[mi][nj][1]);
            float2 v1 = make_float2(acc[mi][nj][2], acc[mi][nj][3]);
            if (HASBIAS) {
                v0.x += bv[nj].x; v0.y += bv[nj].y;
                v1.x += bv[nj].x; v1.y += bv[nj].y;
            }
            if (ADDC) {
                float2 c0 = *(const float2*)&C2[(size_t)r0 * N + cc];
                float2 c1 = *(const float2*)&C2[(size_t)(r0 + 8) * N + cc];
                v0.x += c0.x; v0.y += c0.y;
                v1.x += c1.x; v1.y += c1.y;
            }
            if (RELU) {
                v0.x = fmaxf(v0.x, 0.f); v0.y = fmaxf(v0.y, 0.f);
                v1.x = fmaxf(v1.x, 0.f); v1.y = fmaxf(v1.y, 0.f);
            }
            if (OUTHALF) {
                __half* C = (__half*)Cv;
                *(__half2*)&C[(size_t)r0 * N + cc]       = __floats2half2_rn(v0.x, v0.y);
                *(__half2*)&C[(size_t)(r0 + 8) * N + cc] = __floats2half2_rn(v1.x, v1.y);
            } else {
                float* C = (float*)Cv;
                *(float2*)&C[(size_t)r0 * N + cc]       = v0;
                *(float2*)&C[(size_t)(r0 + 8) * N + cc] = v1;
            }
        }
    }
}

// ---------------------------------------------------------------------------
// Block reduction (256 threads)
// ---------------------------------------------------------------------------
__device__ __forceinline__ float block_sum256(float v)
{
    __shared__ float buf[8];
    int lane = threadIdx.x & 31, wid = threadIdx.x >> 5;
    #pragma unroll
    for (int o = 16; o > 0; o >>= 1) v += __shfl_xor_sync(0xffffffffu, v, o);
    if (lane == 0) buf[wid] = v;
    __syncthreads();
    float r = buf[0] + buf[1] + buf[2] + buf[3] + buf[4] + buf[5] + buf[6] + buf[7];
    __syncthreads();
    return r;
}

// ---------------------------------------------------------------------------
// add + LayerNorm: x = x1 + x2; optionally write fp16 x; out = LN(x) (fp16|fp32)
// ---------------------------------------------------------------------------
template<bool WRITE_PRE, bool OUTHALF>
__global__ void __launch_bounds__(256) add_ln_kernel(
    const float* __restrict__ x1, const float* __restrict__ x2,
    const float* __restrict__ gamma, const float* __restrict__ beta,
    __half* __restrict__ pre, void* __restrict__ out)
{
    const int n = blockIdx.x;
    const int tid = threadIdx.x;
    const size_t base = (size_t)n * HDIM;

    float4 a = ((const float4*)(x1 + base))[tid];
    float4 c = ((const float4*)(x2 + base))[tid];
    float4 x = make_float4(a.x + c.x, a.y + c.y, a.z + c.z, a.w + c.w);
    if (WRITE_PRE) {
        __half2* p = (__half2*)(pre + base) + tid * 2;
        p[0] = __floats2half2_rn(x.x, x.y);
        p[1] = __floats2half2_rn(x.z, x.w);
    }

    float s = x.x + x.y + x.z + x.w;
    s = block_sum256(s);
    const float mu = s * (1.0f / HDIM);

    float d0 = x.x - mu, d1 = x.y - mu, d2 = x.z - mu, d3 = x.w - mu;
    float sq = d0 * d0 + d1 * d1 + d2 * d2 + d3 * d3;
    sq = block_sum256(sq);
    const float rstd = rsqrtf(sq * (1.0f / HDIM) + 1e-12f);

    float4 g4 = ((const float4*)gamma)[tid];
    float4 b4 = ((const float4*)beta)[tid];
    float o0 = d0 * rstd * g4.x + b4.x;
    float o1 = d1 * rstd * g4.y + b4.y;
    float o2 = d2 * rstd * g4.z + b4.z;
    float o3 = d3 * rstd * g4.w + b4.w;
    if (OUTHALF) {
        __half2* p = (__half2*)((__half*)out + base) + tid * 2;
        p[0] = __floats2half2_rn(o0, o1);
        p[1] = __floats2half2_rn(o2, o3);
    } else {
        ((float4*)((float*)out + base))[tid] = make_float4(o0, o1, o2, o3);
    }
}

// ---------------------------------------------------------------------------
// Prep kernels
// ---------------------------------------------------------------------------
__global__ void half_copy_kernel(const float* __restrict__ in,
                                 __half* __restrict__ out, int n)
{
    int i4 = (blockIdx.x * blockDim.x + threadIdx.x) << 2;
    if (i4 >= n) return;
    float4 v = *(const float4*)(in + i4);
    __half2* o = (__half2*)(out + i4);
    o[0] = __floats2half2_rn(v.x, v.y);
    o[1] = __floats2half2_rn(v.z, v.w);
}

__global__ void transpose_half_kernel(const float* __restrict__ in,   // [H,H]
                                      __half* __restrict__ out)       // out[n][k]=in[k][n]
{
    int idx = blockIdx.x * blockDim.x + threadIdx.x;
    if (idx >= HDIM * HDIM) return;
    int nR = idx >> 10, k = idx & (HDIM - 1);
    out[idx] = __float2half_rn(in[(size_t)k * HDIM + nR]);
}

// qkb[k] = sum_j query_b[j] * key_w[j,k]
__global__ void qkb_kernel(const float* __restrict__ qb,
                           const float* __restrict__ kw,
                           float* __restrict__ qkb)
{
    int k = blockIdx.x * blockDim.x + threadIdx.x;
    if (k >= HDIM) return;
    float s = 0.f;
    for (int j = 0; j < HDIM; j++) s += qb[j] * kw[(size_t)j * HDIM + k];
    qkb[k] = s;
}

// uw2[j][h] = up_w[t,h,d]   (j = t*64+d)          [512 x 1024]
__global__ void build_uw2_kernel(const float* __restrict__ up_w,
                                 __half* __restrict__ uw2)
{
    int idx = blockIdx.x * blockDim.x + threadIdx.x;
    if (idx >= TD * HDIM) return;
    int j = idx >> 10, h = idx & (HDIM - 1);
    int t = j >> 6, d = j & 63;
    uw2[idx] = __float2half_rn(up_w[((size_t)t * HDIM + h) * 64 + d]);
}

// uw2T[h][j]: j<512 -> up_w[t,h,d]; 512..519 -> up_b[j-512][h]; else 0  [1024 x 576]
__global__ void build_uw2T_kernel(const float* __restrict__ up_w,
                                  const float* __restrict__ up_b,
                                  __half* __restrict__ uw2T)
{
    int idx = blockIdx.x * blockDim.x + threadIdx.x;
    if (idx >= HDIM * TDBP) return;
    int h = idx / TDBP, j = idx % TDBP;
    float v = 0.0f;
    if (j < TD) {
        int t = j >> 6, d = j & 63;
        v = up_w[((size_t)t * HDIM + h) * 64 + d];
    } else if (j < TD + TTASK) {
        v = up_b[(size_t)(j - TD) * HDIM + h];
    }
    uw2T[idx] = __float2half_rn(v);
}

// ---------------------------------------------------------------------------
// Scores + softmax over tasks + pdr (fp16, stride TDBP, pad zeroed)
// ---------------------------------------------------------------------------
__global__ void __launch_bounds__(256) score_softmax_kernel(
    const __half* __restrict__ dr, const __half* __restrict__ e,
    const __half* __restrict__ qk, const float* __restrict__ up_b,
    __half* __restrict__ pdr)
{
    const int n = blockIdx.x;
    const int tid = threadIdx.x;
    const int w = tid >> 5, l = tid & 31;

    const size_t b512 = (size_t)n * TD;
    float v = __half2float(dr[b512 + w * 64 + l])      * __half2float(e[b512 + w * 64 + l])
            + __half2float(dr[b512 + w * 64 + 32 + l]) * __half2float(e[b512 + w * 64 + 32 + l]);

    const __half* qrow = qk + (size_t)n * HDIM;
    const float* ub = up_b + (size_t)w * HDIM;
    float u = 0.f;
    #pragma unroll 8
    for (int h = l; h < HDIM; h += 32) u += __half2float(qrow[h]) * ub[h];
    v += u;

    #pragma unroll
    for (int o = 16; o > 0; o >>= 1) v += __shfl_xor_sync(0xffffffffu, v, o);

    __shared__ float s[TTASK];
    if (l == 0) s[w] = v;
    __syncthreads();

    float mx = s[0];
    #pragma unroll
    for (int t = 1; t < TTASK; t++) mx = fmaxf(mx, s[t]);
    float p[TTASK]; float sum = 0.f;
    #pragma unroll
    for (int t = 0; t < TTASK; t++) { p[t] = __expf(s[t] - mx); sum += p[t]; }
    const float inv = 1.0f / sum;

    const size_t b = (size_t)n * TDBP;
    #pragma unroll
    for (int r = 0; r < 2; r++) {
        int c = tid + r * 256;
        int t = c >> 6;
        pdr[b + c] = __float2half_rn(p[t] * inv * __half2float(dr[b512 + c]));
    }
    if (tid < TTASK)   pdr[b + TD + tid] = __float2half_rn(p[tid] * inv);
    else if (tid < 64) pdr[b + TD + tid] = __float2half_rn(0.0f);
}

// ---------------------------------------------------------------------------
// Launch
// ---------------------------------------------------------------------------
struct Scratch {
    __half *hsh, *pre, *ain, *dr, *qk, *e, *pdr, *mix;
    __half *dw, *dnw, *qwT, *kwT, *wqk, *vw, *uw2, *uw2T;
    float *h, *fus, *qkb;
};

static constexpr int SMEM_128 = 3 * 2 * 16384;           // 98304 B
static constexpr int SMEM_64  = 3 * (8192 + 16384);      // 73728 B

static Scratch init_once()
{
    Scratch s;
    cudaGetSymbolAddress((void**)&s.hsh,  g_hsh);
    cudaGetSymbolAddress((void**)&s.pre,  g_pre);
    cudaGetSymbolAddress((void**)&s.ain,  g_ain);
    cudaGetSymbolAddress((void**)&s.dr,   g_dr);
    cudaGetSymbolAddress((void**)&s.qk,   g_qk);
    cudaGetSymbolAddress((void**)&s.e,    g_e);
    cudaGetSymbolAddress((void**)&s.pdr,  g_pdr);
    cudaGetSymbolAddress((void**)&s.mix,  g_mix);
    cudaGetSymbolAddress((void**)&s.dw,   g_dw);
    cudaGetSymbolAddress((void**)&s.dnw,  g_dnw);
    cudaGetSymbolAddress((void**)&s.qwT,  g_qwT);
    cudaGetSymbolAddress((void**)&s.kwT,  g_kwT);
    cudaGetSymbolAddress((void**)&s.wqk,  g_wqk);
    cudaGetSymbolAddress((void**)&s.vw,   g_vw);
    cudaGetSymbolAddress((void**)&s.uw2,  g_uw2);
    cudaGetSymbolAddress((void**)&s.uw2T, g_uw2T);
    cudaGetSymbolAddress((void**)&s.h,    g_h);
    cudaGetSymbolAddress((void**)&s.fus,  g_fus);
    cudaGetSymbolAddress((void**)&s.qkb,  g_qkb);
    cudaFuncSetAttribute(gemm_h<128, true,  false, false, false>, cudaFuncAttributeMaxDynamicSharedMemorySize, SMEM_128);
    cudaFuncSetAttribute(gemm_h<128, true,  false, false, true >, cudaFuncAttributeMaxDynamicSharedMemorySize, SMEM_128);
    cudaFuncSetAttribute(gemm_h<128, false, false, true,  true >, cudaFuncAttributeMaxDynamicSharedMemorySize, SMEM_128);
    cudaFuncSetAttribute(gemm_h<128, false, false, false, false>, cudaFuncAttributeMaxDynamicSharedMemorySize, SMEM_128);
    cudaFuncSetAttribute(gemm_h<64,  true,  true,  false, true >, cudaFuncAttributeMaxDynamicSharedMemorySize, SMEM_64);
    cudaFuncSetAttribute(gemm_h<64,  false, false, false, true >, cudaFuncAttributeMaxDynamicSharedMemorySize, SMEM_64);
    return s;
}

extern "C" void kernel_launch(void* const* d_in, const int* in_sizes, int n_in,
                              void* d_out, int out_size)
{
    const float* hs      = (const float*)d_in[0];
    const float* inp     = (const float*)d_in[1];
    const float* dense_w = (const float*)d_in[2];
    const float* dense_b = (const float*)d_in[3];
    const float* ln_g    = (const float*)d_in[4];
    const float* ln_b    = (const float*)d_in[5];
    const float* down_w  = (const float*)d_in[6];
    const float* down_b  = (const float*)d_in[7];
    const float* up_w    = (const float*)d_in[8];
    const float* up_b    = (const float*)d_in[9];
    const float* key_w   = (const float*)d_in[10];  // key_b cancels in softmax
    const float* query_w = (const float*)d_in[12];
    const float* query_b = (const float*)d_in[13];
    const float* value_w = (const float*)d_in[14];
    float* out = (float*)d_out;

    static Scratch s = init_once();

    dim3 blk(256);

    // 0. fp16 conversions / layouts
    half_copy_kernel<<<NTOK * IDIM / 4 / 256, blk>>>(hs, s.hsh, NTOK * IDIM);
    half_copy_kernel<<<HDIM * IDIM / 4 / 256, blk>>>(dense_w, s.dw, HDIM * IDIM);
    half_copy_kernel<<<TD * HDIM / 4 / 256, blk>>>(down_w, s.dnw, TD * HDIM);
    half_copy_kernel<<<HDIM * HDIM / 4 / 256, blk>>>(value_w, s.vw, HDIM * HDIM);
    transpose_half_kernel<<<HDIM * HDIM / 256, blk>>>(query_w, s.qwT);
    transpose_half_kernel<<<HDIM * HDIM / 256, blk>>>(key_w, s.kwT);
    build_uw2_kernel<<<TD * HDIM / 256, blk>>>(up_w, s.uw2);
    build_uw2T_kernel<<<(HDIM * TDBP + 255) / 256, blk>>>(up_w, up_b, s.uw2T);
    qkb_kernel<<<HDIM / 256, blk>>>(query_b, key_w, s.qkb);

    // 0b. W_qk[k,i] = sum_j Kw[j,k] Qw[j,i]  (= kwT @ qwT^T)   [1024,1024], K=1024
    gemm_h<64, false, false, false, true><<<dim3(8, 16), blk, SMEM_64>>>(
        s.kwT, s.qwT, nullptr, nullptr, s.wqk, HDIM, HDIM);

    // 1. h = hs @ dense_w^T + dense_b            [4096,1024], K=4096 (fp32 out)
    gemm_h<128, true, false, false, false><<<dim3(8, 32), blk, SMEM_128>>>(
        s.hsh, s.dw, dense_b, nullptr, s.h, HDIM, IDIM);

    // 2. pre = h16(inp + h); ain = h16(LN(.))
    add_ln_kernel<true, true><<<NTOK, blk>>>(inp, s.h, ln_g, ln_b, s.pre, s.ain);

    // 3. dr = relu(ain @ down_w^T + down_b)      [4096,512], K=1024 (MT=64, full chip)
    gemm_h<64, true, true, false, true><<<dim3(4, 64), blk, SMEM_64>>>(
        s.ain, s.dnw, down_b, nullptr, s.dr, TD, HDIM);

    // 4. qk = pre @ W_qk^T + qkb                 [4096,1024], K=1024
    gemm_h<128, true, false, false, true><<<dim3(8, 32), blk, SMEM_128>>>(
        s.pre, s.wqk, s.qkb, nullptr, s.qk, HDIM, HDIM);

    // 5. e = qk @ uw2^T                          [4096,512], K=1024 (MT=64)
    gemm_h<64, false, false, false, true><<<dim3(4, 64), blk, SMEM_64>>>(
        s.qk, s.uw2, nullptr, nullptr, s.e, TD, HDIM);

    // 6. scores + softmax + pdr
    score_softmax_kernel<<<NTOK, blk>>>(s.dr, s.e, s.qk, up_b, s.pdr);

    // 7. mix = pdr @ uw2T^T + h                  [4096,1024], K=576
    gemm_h<128, false, false, true, true><<<dim3(8, 32), blk, SMEM_128>>>(
        s.pdr, s.uw2T, nullptr, s.h, s.mix, HDIM, TDBP);

    // 8. fus = mix @ value_w^T                   [4096,1024], K=1024 (fp32 out)
    gemm_h<128, false, false, false, false><<<dim3(8, 32), blk, SMEM_128>>>(
        s.mix, s.vw, nullptr, nullptr, s.fus, HDIM, HDIM);

    // 9. out = LN(inp + fus)
    add_ln_kernel<false, false><<<NTOK, blk>>>(inp, s.fus, ln_g, ln_b, nullptr, out);
}